// round 1
// baseline (speedup 1.0000x reference)
#include <cuda_runtime.h>
#include <cuda_bf16.h>

#define N_NODES  100000
#define N_EDGES  400000
#define N_GRAPHS 2000
#define F_EDGE   8
#define HID      16

// ---------------- scratch (static device globals; no allocation) ----------------
__device__ float g_agg1[N_NODES * 32];   // 12.8 MB
__device__ float g_h1  [N_NODES * 32];   // 12.8 MB
__device__ float g_agg2[N_NODES * 16];   // 6.4 MB
__device__ float g_h2  [N_NODES * 16];   // 6.4 MB
__device__ float g_pool[N_GRAPHS * 16];
__device__ float g_cnt [N_GRAPHS];

// ---------------- zero scratch ----------------
__global__ void zero_all_kernel() {
    int i = blockIdx.x * blockDim.x + threadIdx.x;
    if (i < N_NODES * 32) g_agg1[i] = 0.f;
    if (i < N_NODES * 16) g_agg2[i] = 0.f;
    if (i < N_GRAPHS * 16) g_pool[i] = 0.f;
    if (i < N_GRAPHS) g_cnt[i] = 0.f;
}

// ---------------- fused NNConv edge kernel ----------------
// msg[e,o] = sum_h hid[e,h] * (sum_i x[src,i] * W2[h, i*FOUT+o])
//          + sum_i x[src,i] * b2[i*FOUT+o]
// hid[e,h] = relu(b1[h] + sum_j ea[e,j]*W1[j,h])  (recomputed per h, cheap)
template <int FIN, int FOUT>
__global__ void __launch_bounds__(256)
edge_kernel(const float* __restrict__ x,
            const float* __restrict__ ea,
            const int*   __restrict__ ei,
            const float* __restrict__ w1, const float* __restrict__ b1,
            const float* __restrict__ w2, const float* __restrict__ b2,
            float* __restrict__ agg)
{
    __shared__ __align__(16) float sW2[HID * FIN * FOUT];   // 32 KB
    __shared__ __align__(16) float sB2[FIN * FOUT];
    __shared__ float sW1[F_EDGE * HID];
    __shared__ float sB1[HID];

    for (int idx = threadIdx.x; idx < HID * FIN * FOUT; idx += 256) sW2[idx] = w2[idx];
    for (int idx = threadIdx.x; idx < FIN * FOUT;       idx += 256) sB2[idx] = b2[idx];
    if (threadIdx.x < F_EDGE * HID) sW1[threadIdx.x] = w1[threadIdx.x];
    if (threadIdx.x < HID)          sB1[threadIdx.x] = b1[threadIdx.x];
    __syncthreads();

    const int e = blockIdx.x * 256 + threadIdx.x;
    if (e >= N_EDGES) return;

    float eav[F_EDGE];
    #pragma unroll
    for (int j = 0; j < F_EDGE; j++) eav[j] = ea[e * F_EDGE + j];

    const int src = ei[e];
    const int dst = ei[N_EDGES + e];

    float xv[FIN];
    #pragma unroll
    for (int i = 0; i < FIN; i++) xv[i] = x[src * FIN + i];

    float msg[FOUT];
    #pragma unroll
    for (int o = 0; o < FOUT; o++) msg[o] = 0.f;

    // bias-theta term: sum_i x_i * b2[i*FOUT+o]
    #pragma unroll
    for (int i = 0; i < FIN; i++) {
        const float xi = xv[i];
        const float4* p = (const float4*)&sB2[i * FOUT];
        #pragma unroll
        for (int o4 = 0; o4 < FOUT / 4; o4++) {
            float4 w = p[o4];
            msg[o4*4+0] += xi * w.x;
            msg[o4*4+1] += xi * w.y;
            msg[o4*4+2] += xi * w.z;
            msg[o4*4+3] += xi * w.w;
        }
    }

    // main bilinear contraction
    #pragma unroll 1
    for (int h = 0; h < HID; h++) {
        // hid[h] recomputed on the fly (8 FMA)
        float s = sB1[h];
        #pragma unroll
        for (int j = 0; j < F_EDGE; j++) s += eav[j] * sW1[j * HID + h];
        const float hh = fmaxf(s, 0.f);

        #pragma unroll
        for (int i = 0; i < FIN; i++) {
            const float c = hh * xv[i];
            const float4* p = (const float4*)&sW2[(h * FIN + i) * FOUT];
            #pragma unroll
            for (int o4 = 0; o4 < FOUT / 4; o4++) {
                float4 w = p[o4];
                msg[o4*4+0] += c * w.x;
                msg[o4*4+1] += c * w.y;
                msg[o4*4+2] += c * w.z;
                msg[o4*4+3] += c * w.w;
            }
        }
    }

    float* dstp = agg + (size_t)dst * FOUT;
    #pragma unroll
    for (int o = 0; o < FOUT; o++) atomicAdd(&dstp[o], msg[o]);
}

// ---------------- node update: out = relu(x @ root + agg + bias) ----------------
template <int FIN, int FOUT>
__global__ void __launch_bounds__(256)
node_kernel(const float* __restrict__ xin,
            const float* __restrict__ agg,
            const float* __restrict__ root,
            const float* __restrict__ bias,
            float* __restrict__ out)
{
    __shared__ __align__(16) float sR[FIN * FOUT];
    __shared__ float sB[FOUT];
    for (int idx = threadIdx.x; idx < FIN * FOUT; idx += 256) sR[idx] = root[idx];
    if (threadIdx.x < FOUT) sB[threadIdx.x] = bias[threadIdx.x];
    __syncthreads();

    const int n = blockIdx.x * 256 + threadIdx.x;
    if (n >= N_NODES) return;

    float xv[FIN];
    #pragma unroll
    for (int i = 0; i < FIN; i++) xv[i] = xin[n * FIN + i];

    float acc[FOUT];
    #pragma unroll
    for (int o = 0; o < FOUT; o++) acc[o] = sB[o] + agg[(size_t)n * FOUT + o];

    #pragma unroll
    for (int i = 0; i < FIN; i++) {
        const float xi = xv[i];
        const float4* p = (const float4*)&sR[i * FOUT];
        #pragma unroll
        for (int o4 = 0; o4 < FOUT / 4; o4++) {
            float4 w = p[o4];
            acc[o4*4+0] += xi * w.x;
            acc[o4*4+1] += xi * w.y;
            acc[o4*4+2] += xi * w.z;
            acc[o4*4+3] += xi * w.w;
        }
    }
    #pragma unroll
    for (int o = 0; o < FOUT; o++)
        out[(size_t)n * FOUT + o] = fmaxf(acc[o], 0.f);
}

// ---------------- mean-pool accumulation ----------------
__global__ void pool_kernel(const int* __restrict__ batch) {
    const int n = blockIdx.x * blockDim.x + threadIdx.x;
    if (n >= N_NODES) return;
    const int g = batch[n];
    #pragma unroll
    for (int o = 0; o < 16; o++)
        atomicAdd(&g_pool[g * 16 + o], g_h2[(size_t)n * 16 + o]);
    atomicAdd(&g_cnt[g], 1.0f);
}

// ---------------- readout MLP: relu(p @ l1w + l1b) @ l2w + l2b ----------------
__global__ void readout_kernel(const float* __restrict__ l1w, const float* __restrict__ l1b,
                               const float* __restrict__ l2w, const float* __restrict__ l2b,
                               float* __restrict__ out)
{
    const int g = blockIdx.x * blockDim.x + threadIdx.x;
    if (g >= N_GRAPHS) return;
    const float inv = 1.0f / fmaxf(g_cnt[g], 1.0f);
    float p[16];
    #pragma unroll
    for (int o = 0; o < 16; o++) p[o] = g_pool[g * 16 + o] * inv;
    float acc = l2b[0];
    #pragma unroll
    for (int j = 0; j < 8; j++) {
        float s = l1b[j];
        #pragma unroll
        for (int o = 0; o < 16; o++) s += p[o] * l1w[o * 8 + j];
        acc += fmaxf(s, 0.f) * l2w[j];
    }
    out[g] = acc;
}

// ---------------- launch ----------------
extern "C" void kernel_launch(void* const* d_in, const int* in_sizes, int n_in,
                              void* d_out, int out_size)
{
    const float* x      = (const float*)d_in[0];
    const float* ea     = (const float*)d_in[1];
    const int*   ei     = (const int*)  d_in[2];
    const int*   batch  = (const int*)  d_in[3];
    const float* nn1_w1 = (const float*)d_in[4];
    const float* nn1_b1 = (const float*)d_in[5];
    const float* nn1_w2 = (const float*)d_in[6];
    const float* nn1_b2 = (const float*)d_in[7];
    const float* root1  = (const float*)d_in[8];
    const float* bias1  = (const float*)d_in[9];
    const float* nn2_w1 = (const float*)d_in[10];
    const float* nn2_b1 = (const float*)d_in[11];
    const float* nn2_w2 = (const float*)d_in[12];
    const float* nn2_b2 = (const float*)d_in[13];
    const float* root2  = (const float*)d_in[14];
    const float* bias2  = (const float*)d_in[15];
    const float* lin1_w = (const float*)d_in[16];
    const float* lin1_b = (const float*)d_in[17];
    const float* lin2_w = (const float*)d_in[18];
    const float* lin2_b = (const float*)d_in[19];
    float* out = (float*)d_out;

    float *agg1, *h1, *agg2, *h2;
    cudaGetSymbolAddress((void**)&agg1, g_agg1);
    cudaGetSymbolAddress((void**)&h1,   g_h1);
    cudaGetSymbolAddress((void**)&agg2, g_agg2);
    cudaGetSymbolAddress((void**)&h2,   g_h2);

    zero_all_kernel<<<(N_NODES * 32 + 255) / 256, 256>>>();

    const int egrid = (N_EDGES + 255) / 256;
    const int ngrid = (N_NODES + 255) / 256;

    // layer 1: F_NODE=16 -> H1=32
    edge_kernel<16, 32><<<egrid, 256>>>(x, ea, ei, nn1_w1, nn1_b1, nn1_w2, nn1_b2, agg1);
    node_kernel<16, 32><<<ngrid, 256>>>(x, agg1, root1, bias1, h1);

    // layer 2: H1=32 -> H2=16
    edge_kernel<32, 16><<<egrid, 256>>>(h1, ea, ei, nn2_w1, nn2_b1, nn2_w2, nn2_b2, agg2);
    node_kernel<32, 16><<<ngrid, 256>>>(h1, agg2, root2, bias2, h2);

    // pooling + readout
    pool_kernel<<<ngrid, 256>>>(batch);
    readout_kernel<<<(N_GRAPHS + 255) / 256, 256>>>(lin1_w, lin1_b, lin2_w, lin2_b, out);
}

// round 2
// speedup vs baseline: 1.4674x; 1.4674x over previous
#include <cuda_runtime.h>
#include <cuda_bf16.h>

#define N_NODES  100000
#define N_EDGES  400000
#define N_GRAPHS 2000
#define F_EDGE   8
#define HID      16

// P layout: [n, h, o] with h in 0..16 (row 16 = b2 bias row, coefficient 1.0)
#define P1_HROWS 17
#define P1_FOUT  32
#define P1_STRIDE (P1_HROWS * P1_FOUT)   // 544
#define P2_HROWS 17
#define P2_FOUT  16
#define P2_STRIDE (P2_HROWS * P2_FOUT)   // 272

// ---------------- scratch (static device globals; no allocation) ----------------
__device__ float g_P1  [N_NODES * P1_STRIDE];  // ~217 MB
__device__ float g_P2  [N_NODES * P2_STRIDE];  // ~109 MB
__device__ float g_agg1[N_NODES * 32];
__device__ float g_h1  [N_NODES * 32];
__device__ float g_agg2[N_NODES * 16];
__device__ float g_h2  [N_NODES * 16];
__device__ float g_pool[N_GRAPHS * 16];
__device__ float g_cnt [N_GRAPHS];

// ---------------- zero scratch ----------------
__global__ void zero_all_kernel() {
    int i = blockIdx.x * blockDim.x + threadIdx.x;
    if (i < N_NODES * 32) g_agg1[i] = 0.f;
    if (i < N_NODES * 16) g_agg2[i] = 0.f;
    if (i < N_GRAPHS * 16) g_pool[i] = 0.f;
    if (i < N_GRAPHS) g_cnt[i] = 0.f;
}

// ---------------- P precompute: P[n,h,o] = sum_i x[n,i]*W2[h, i*FOUT+o] ----------------
// Layer 1: FIN=16, FOUT=32. Block 256 threads: o = tid%32, pair p = tid/32 (8 pairs),
// each thread handles 2 nodes so every smem weight load is amortized over 2 FMAs x2.
__global__ void __launch_bounds__(256)
p1_kernel(const float* __restrict__ x,
          const float* __restrict__ w2, const float* __restrict__ b2)
{
    __shared__ float sW2[HID * 16 * 32];   // 32 KB
    __shared__ float sB2[16 * 32];
    for (int idx = threadIdx.x; idx < HID * 512; idx += 256) sW2[idx] = w2[idx];
    for (int idx = threadIdx.x; idx < 512;       idx += 256) sB2[idx] = b2[idx];
    __syncthreads();

    const int o  = threadIdx.x & 31;
    const int p  = threadIdx.x >> 5;
    const int n0 = blockIdx.x * 16 + p * 2;
    const int n1 = n0 + 1;

    float x0[16], x1[16];
    #pragma unroll
    for (int i = 0; i < 16; i++) { x0[i] = x[n0*16+i]; x1[i] = x[n1*16+i]; }

    float* P0 = g_P1 + (size_t)n0 * P1_STRIDE + o;
    float* P1p = g_P1 + (size_t)n1 * P1_STRIDE + o;

    #pragma unroll
    for (int h = 0; h < HID; h++) {
        float a0 = 0.f, a1 = 0.f;
        #pragma unroll
        for (int i = 0; i < 16; i++) {
            float w = sW2[h*512 + i*32 + o];
            a0 += x0[i] * w; a1 += x1[i] * w;
        }
        P0[h*32] = a0; P1p[h*32] = a1;
    }
    { // bias row
        float a0 = 0.f, a1 = 0.f;
        #pragma unroll
        for (int i = 0; i < 16; i++) {
            float w = sB2[i*32 + o];
            a0 += x0[i] * w; a1 += x1[i] * w;
        }
        P0[16*32] = a0; P1p[16*32] = a1;
    }
}

// Layer 2: FIN=32, FOUT=16. o = tid%16, pair p = tid/16 (16 pairs), 2 nodes/thread.
__global__ void __launch_bounds__(256)
p2_kernel(const float* __restrict__ xin,
          const float* __restrict__ w2, const float* __restrict__ b2)
{
    __shared__ float sW2[HID * 32 * 16];   // 32 KB
    __shared__ float sB2[32 * 16];
    for (int idx = threadIdx.x; idx < HID * 512; idx += 256) sW2[idx] = w2[idx];
    for (int idx = threadIdx.x; idx < 512;       idx += 256) sB2[idx] = b2[idx];
    __syncthreads();

    const int o  = threadIdx.x & 15;
    const int p  = threadIdx.x >> 4;
    const int n0 = blockIdx.x * 32 + p * 2;
    const int n1 = n0 + 1;

    float x0[32], x1[32];
    #pragma unroll
    for (int i = 0; i < 32; i++) { x0[i] = xin[n0*32+i]; x1[i] = xin[n1*32+i]; }

    float* P0 = g_P2 + (size_t)n0 * P2_STRIDE + o;
    float* P1p = g_P2 + (size_t)n1 * P2_STRIDE + o;

    #pragma unroll
    for (int h = 0; h < HID; h++) {
        float a0 = 0.f, a1 = 0.f;
        #pragma unroll
        for (int i = 0; i < 32; i++) {
            float w = sW2[h*512 + i*16 + o];
            a0 += x0[i] * w; a1 += x1[i] * w;
        }
        P0[h*16] = a0; P1p[h*16] = a1;
    }
    {
        float a0 = 0.f, a1 = 0.f;
        #pragma unroll
        for (int i = 0; i < 32; i++) {
            float w = sB2[i*16 + o];
            a0 += x0[i] * w; a1 += x1[i] * w;
        }
        P0[16*16] = a0; P1p[16*16] = a1;
    }
}

// ---------------- edge kernels: msg[e,o] = sum_h hid[e,h] * P[src,h,o] ----------------
// Layer 1: one warp per edge; lane = output channel o (32 outputs).
__global__ void __launch_bounds__(256)
edge1_kernel(const float* __restrict__ ea,
             const int*   __restrict__ ei,
             const float* __restrict__ w1, const float* __restrict__ b1)
{
    const int w = (blockIdx.x * 256 + threadIdx.x) >> 5;
    const int lane = threadIdx.x & 31;
    if (w >= N_EDGES) return;
    const int e = w;

    const int src = ei[e];
    const int dst = ei[N_EDGES + e];

    // lanes 0..15 compute hidden h=lane
    float hid = 0.f;
    if (lane < HID) {
        float s = b1[lane];
        #pragma unroll
        for (int j = 0; j < F_EDGE; j++) s += ea[e*F_EDGE + j] * w1[j*HID + lane];
        hid = fmaxf(s, 0.f);
    }

    const float* P = g_P1 + (size_t)src * P1_STRIDE + lane;
    float msg = P[16*32];   // bias row, coefficient 1
    #pragma unroll
    for (int h = 0; h < HID; h++)
        msg += __shfl_sync(0xffffffffu, hid, h) * P[h*32];

    atomicAdd(&g_agg1[(size_t)dst * 32 + lane], msg);
}

// Layer 2: one warp per 2 edges; half-warp per edge, o = lane&15.
__global__ void __launch_bounds__(256)
edge2_kernel(const float* __restrict__ ea,
             const int*   __restrict__ ei,
             const float* __restrict__ w1, const float* __restrict__ b1)
{
    const int w = (blockIdx.x * 256 + threadIdx.x) >> 5;
    const int lane = threadIdx.x & 31;
    const int half = lane >> 4;
    const int o = lane & 15;
    const int e = 2 * w + half;
    if (e >= N_EDGES) return;

    const int src = ei[e];
    const int dst = ei[N_EDGES + e];

    // every lane computes hidden h=o for its half's edge
    float s = b1[o];
    #pragma unroll
    for (int j = 0; j < F_EDGE; j++) s += ea[e*F_EDGE + j] * w1[j*HID + o];
    const float hid = fmaxf(s, 0.f);

    const float* P = g_P2 + (size_t)src * P2_STRIDE + o;
    float msg = P[16*16];
    #pragma unroll
    for (int h = 0; h < HID; h++)
        msg += __shfl_sync(0xffffffffu, hid, h, 16) * P[h*16];

    atomicAdd(&g_agg2[(size_t)dst * 16 + o], msg);
}

// ---------------- node update: out = relu(x @ root + agg + bias) ----------------
template <int FIN, int FOUT>
__global__ void __launch_bounds__(256)
node_kernel(const float* __restrict__ xin,
            const float* __restrict__ agg,
            const float* __restrict__ root,
            const float* __restrict__ bias,
            float* __restrict__ out)
{
    __shared__ __align__(16) float sR[FIN * FOUT];
    __shared__ float sB[FOUT];
    for (int idx = threadIdx.x; idx < FIN * FOUT; idx += 256) sR[idx] = root[idx];
    if (threadIdx.x < FOUT) sB[threadIdx.x] = bias[threadIdx.x];
    __syncthreads();

    const int n = blockIdx.x * 256 + threadIdx.x;
    if (n >= N_NODES) return;

    float xv[FIN];
    #pragma unroll
    for (int i = 0; i < FIN; i++) xv[i] = xin[n * FIN + i];

    float acc[FOUT];
    #pragma unroll
    for (int o = 0; o < FOUT; o++) acc[o] = sB[o] + agg[(size_t)n * FOUT + o];

    #pragma unroll
    for (int i = 0; i < FIN; i++) {
        const float xi = xv[i];
        #pragma unroll
        for (int o = 0; o < FOUT; o++) acc[o] += xi * sR[i * FOUT + o];
    }
    #pragma unroll
    for (int o = 0; o < FOUT; o++)
        out[(size_t)n * FOUT + o] = fmaxf(acc[o], 0.f);
}

// ---------------- mean-pool accumulation ----------------
__global__ void pool_kernel(const int* __restrict__ batch) {
    const int n = blockIdx.x * blockDim.x + threadIdx.x;
    if (n >= N_NODES) return;
    const int g = batch[n];
    #pragma unroll
    for (int o = 0; o < 16; o++)
        atomicAdd(&g_pool[g * 16 + o], g_h2[(size_t)n * 16 + o]);
    atomicAdd(&g_cnt[g], 1.0f);
}

// ---------------- readout MLP ----------------
__global__ void readout_kernel(const float* __restrict__ l1w, const float* __restrict__ l1b,
                               const float* __restrict__ l2w, const float* __restrict__ l2b,
                               float* __restrict__ out)
{
    const int g = blockIdx.x * blockDim.x + threadIdx.x;
    if (g >= N_GRAPHS) return;
    const float inv = 1.0f / fmaxf(g_cnt[g], 1.0f);
    float p[16];
    #pragma unroll
    for (int o = 0; o < 16; o++) p[o] = g_pool[g * 16 + o] * inv;
    float acc = l2b[0];
    #pragma unroll
    for (int j = 0; j < 8; j++) {
        float s = l1b[j];
        #pragma unroll
        for (int o = 0; o < 16; o++) s += p[o] * l1w[o * 8 + j];
        acc += fmaxf(s, 0.f) * l2w[j];
    }
    out[g] = acc;
}

// ---------------- launch ----------------
extern "C" void kernel_launch(void* const* d_in, const int* in_sizes, int n_in,
                              void* d_out, int out_size)
{
    const float* x      = (const float*)d_in[0];
    const float* ea     = (const float*)d_in[1];
    const int*   ei     = (const int*)  d_in[2];
    const int*   batch  = (const int*)  d_in[3];
    const float* nn1_w1 = (const float*)d_in[4];
    const float* nn1_b1 = (const float*)d_in[5];
    const float* nn1_w2 = (const float*)d_in[6];
    const float* nn1_b2 = (const float*)d_in[7];
    const float* root1  = (const float*)d_in[8];
    const float* bias1  = (const float*)d_in[9];
    const float* nn2_w1 = (const float*)d_in[10];
    const float* nn2_b1 = (const float*)d_in[11];
    const float* nn2_w2 = (const float*)d_in[12];
    const float* nn2_b2 = (const float*)d_in[13];
    const float* root2  = (const float*)d_in[14];
    const float* bias2  = (const float*)d_in[15];
    const float* lin1_w = (const float*)d_in[16];
    const float* lin1_b = (const float*)d_in[17];
    const float* lin2_w = (const float*)d_in[18];
    const float* lin2_b = (const float*)d_in[19];
    float* out = (float*)d_out;

    float *agg1, *h1, *agg2, *h2;
    cudaGetSymbolAddress((void**)&agg1, g_agg1);
    cudaGetSymbolAddress((void**)&h1,   g_h1);
    cudaGetSymbolAddress((void**)&agg2, g_agg2);
    cudaGetSymbolAddress((void**)&h2,   g_h2);

    zero_all_kernel<<<(N_NODES * 32 + 255) / 256, 256>>>();

    const int ngrid = (N_NODES + 255) / 256;

    // ---- layer 1: 16 -> 32 ----
    p1_kernel<<<N_NODES / 16, 256>>>(x, nn1_w2, nn1_b2);
    edge1_kernel<<<(N_EDGES * 32 + 255) / 256, 256>>>(ea, ei, nn1_w1, nn1_b1);
    node_kernel<16, 32><<<ngrid, 256>>>(x, agg1, root1, bias1, h1);

    // ---- layer 2: 32 -> 16 ----
    p2_kernel<<<N_NODES / 32, 256>>>(h1, nn2_w2, nn2_b2);
    edge2_kernel<<<(N_EDGES / 2 * 32 + 255) / 256, 256>>>(ea, ei, nn2_w1, nn2_b1);
    node_kernel<32, 16><<<ngrid, 256>>>(h1, agg2, root2, bias2, h2);

    // ---- pooling + readout ----
    pool_kernel<<<ngrid, 256>>>(batch);
    readout_kernel<<<(N_GRAPHS + 255) / 256, 256>>>(lin1_w, lin1_b, lin2_w, lin2_b, out);
}

// round 4
// speedup vs baseline: 2.0786x; 1.4166x over previous
#include <cuda_runtime.h>
#include <cuda_fp16.h>

#define N_NODES  100000
#define N_EDGES  400000
#define N_GRAPHS 2000
#define F_EDGE   8
#define HID      16

// P stored as half2 pairs over h: row k holds (h=2k, h=2k+1), k=8 holds (bias,0)
#define P1_K      9
#define P1_FOUT   32
#define P1_STRIDE (P1_K * P1_FOUT)   // 288 half2 per node (~115 MB total)
#define P2_K      9
#define P2_FOUT   16
#define P2_STRIDE (P2_K * P2_FOUT)   // 144 half2 per node (~57.6 MB total)

// ---------------- scratch (static device globals; no allocation) ----------------
__device__ __half2 g_P1h[N_NODES * P1_STRIDE];
__device__ __half2 g_P2h[N_NODES * P2_STRIDE];
__device__ float   g_agg1[N_NODES * 32];
__device__ float   g_h1  [N_NODES * 32];
__device__ float   g_agg2[N_NODES * 16];
__device__ float   g_pool[N_GRAPHS * 16];
__device__ float   g_cnt [N_GRAPHS];

// ---------------- zero scratch ----------------
__global__ void zero_all_kernel() {
    int i = blockIdx.x * blockDim.x + threadIdx.x;
    if (i < N_NODES * 32) g_agg1[i] = 0.f;
    if (i < N_NODES * 16) g_agg2[i] = 0.f;
    if (i < N_GRAPHS * 16) g_pool[i] = 0.f;
    if (i < N_GRAPHS) g_cnt[i] = 0.f;
}

// ---------------- P1: P[n,h,o] = sum_i x[n,i]*W2[h,i*32+o], fp16 pairs ----------------
// 256 threads: o = tid&31, p = tid>>5 (8 pairs), 2 nodes per thread -> 16 nodes/block
__global__ void __launch_bounds__(256)
p1_kernel(const float* __restrict__ x,
          const float* __restrict__ w2, const float* __restrict__ b2)
{
    __shared__ float sW2[HID * 512];   // 32 KB
    __shared__ float sB2[512];
    for (int idx = threadIdx.x; idx < HID * 512; idx += 256) sW2[idx] = w2[idx];
    for (int idx = threadIdx.x; idx < 512;       idx += 256) sB2[idx] = b2[idx];
    __syncthreads();

    const int o  = threadIdx.x & 31;
    const int p  = threadIdx.x >> 5;
    const int n0 = blockIdx.x * 16 + p * 2;
    const int n1 = n0 + 1;

    float x0[16], x1[16];
    #pragma unroll
    for (int i = 0; i < 16; i++) { x0[i] = x[n0*16+i]; x1[i] = x[n1*16+i]; }

    __half2* P0 = g_P1h + (size_t)n0 * P1_STRIDE + o;
    __half2* P1 = g_P1h + (size_t)n1 * P1_STRIDE + o;

    #pragma unroll
    for (int k = 0; k < 8; k++) {
        float a0e = 0.f, a0o = 0.f, a1e = 0.f, a1o = 0.f;
        #pragma unroll
        for (int i = 0; i < 16; i++) {
            float we = sW2[(2*k)  *512 + i*32 + o];
            float wo = sW2[(2*k+1)*512 + i*32 + o];
            a0e += x0[i]*we; a0o += x0[i]*wo;
            a1e += x1[i]*we; a1o += x1[i]*wo;
        }
        P0[k*32] = __floats2half2_rn(a0e, a0o);
        P1[k*32] = __floats2half2_rn(a1e, a1o);
    }
    { // bias row
        float a0 = 0.f, a1 = 0.f;
        #pragma unroll
        for (int i = 0; i < 16; i++) {
            float w = sB2[i*32 + o];
            a0 += x0[i]*w; a1 += x1[i]*w;
        }
        P0[8*32] = __floats2half2_rn(a0, 0.f);
        P1[8*32] = __floats2half2_rn(a1, 0.f);
    }
}

// ---------------- edge1: warp per edge, lane = o ----------------
__global__ void __launch_bounds__(256)
edge1_kernel(const float* __restrict__ ea,
             const int*   __restrict__ ei,
             const float* __restrict__ w1, const float* __restrict__ b1)
{
    const int e = (blockIdx.x * 256 + threadIdx.x) >> 5;
    const int lane = threadIdx.x & 31;
    if (e >= N_EDGES) return;

    const int src = ei[e];
    const int dst = ei[N_EDGES + e];

    float hid = 0.f;
    if (lane < HID) {
        float s = b1[lane];
        #pragma unroll
        for (int j = 0; j < F_EDGE; j++) s += ea[e*F_EDGE + j] * w1[j*HID + lane];
        hid = fmaxf(s, 0.f);
    }

    const __half2* P = g_P1h + (size_t)src * P1_STRIDE + lane;
    float msg = __half22float2(P[8*32]).x;   // bias row
    #pragma unroll
    for (int k = 0; k < 8; k++) {
        float2 f = __half22float2(P[k*32]);
        msg += __shfl_sync(0xffffffffu, hid, 2*k)   * f.x;
        msg += __shfl_sync(0xffffffffu, hid, 2*k+1) * f.y;
    }
    atomicAdd(&g_agg1[(size_t)dst * 32 + lane], msg);
}

// ---------------- fused node1 + P2: h1 = relu(x@root1 + agg1 + bias1); P2 = h1-contraction ----------------
// 32 nodes per block, 256 threads
__global__ void __launch_bounds__(256)
node1_p2_kernel(const float* __restrict__ x,
                const float* __restrict__ root1, const float* __restrict__ bias1,
                const float* __restrict__ w2,    const float* __restrict__ b2)
{
    __shared__ float sX [32 * 16];
    __shared__ float sR1[16 * 32];
    __shared__ float sB1[32];
    __shared__ float sW2[HID * 512];   // 32 KB  (layer2 W2: [16][32*16])
    __shared__ float sB2[512];
    __shared__ float sH1[32 * 33];

    const int b = blockIdx.x;
    const int tid = threadIdx.x;

    for (int idx = tid; idx < 512; idx += 256) {
        sX [idx] = x[(size_t)b * 512 + idx];
        sR1[idx] = root1[idx];
        sB2[idx] = b2[idx];
    }
    if (tid < 32) sB1[tid] = bias1[tid];
    for (int idx = tid; idx < HID * 512; idx += 256) sW2[idx] = w2[idx];
    __syncthreads();

    // part A: h1 for 32 nodes x 32 outputs = 1024 items
    #pragma unroll
    for (int it = 0; it < 4; it++) {
        const int w  = it * 256 + tid;
        const int nl = w >> 5;
        const int o  = w & 31;
        const int n  = b * 32 + nl;
        float acc = sB1[o] + g_agg1[(size_t)n * 32 + o];
        #pragma unroll
        for (int i = 0; i < 16; i++) acc += sX[nl*16+i] * sR1[i*32+o];
        const float v = fmaxf(acc, 0.f);
        sH1[nl*33 + o] = v;
        g_h1[(size_t)n * 32 + o] = v;
    }
    __syncthreads();

    // part B: P2 for these nodes. o = tid&15, p = tid>>4 -> nodes 2p, 2p+1
    const int o  = tid & 15;
    const int p  = tid >> 4;
    const int nl0 = 2*p, nl1 = 2*p + 1;
    const int n0 = b * 32 + nl0;
    const int n1 = n0 + 1;

    float x0[32], x1[32];
    #pragma unroll
    for (int i = 0; i < 32; i++) { x0[i] = sH1[nl0*33+i]; x1[i] = sH1[nl1*33+i]; }

    __half2* P0 = g_P2h + (size_t)n0 * P2_STRIDE + o;
    __half2* P1 = g_P2h + (size_t)n1 * P2_STRIDE + o;

    #pragma unroll
    for (int k = 0; k < 8; k++) {
        float a0e = 0.f, a0o = 0.f, a1e = 0.f, a1o = 0.f;
        #pragma unroll
        for (int i = 0; i < 32; i++) {
            float we = sW2[(2*k)  *512 + i*16 + o];
            float wo = sW2[(2*k+1)*512 + i*16 + o];
            a0e += x0[i]*we; a0o += x0[i]*wo;
            a1e += x1[i]*we; a1o += x1[i]*wo;
        }
        P0[k*16] = __floats2half2_rn(a0e, a0o);
        P1[k*16] = __floats2half2_rn(a1e, a1o);
    }
    {
        float a0 = 0.f, a1 = 0.f;
        #pragma unroll
        for (int i = 0; i < 32; i++) {
            float w = sB2[i*16 + o];
            a0 += x0[i]*w; a1 += x1[i]*w;
        }
        P0[8*16] = __floats2half2_rn(a0, 0.f);
        P1[8*16] = __floats2half2_rn(a1, 0.f);
    }
}

// ---------------- edge2: half-warp per edge, o = lane&15 ----------------
__global__ void __launch_bounds__(256)
edge2_kernel(const float* __restrict__ ea,
             const int*   __restrict__ ei,
             const float* __restrict__ w1, const float* __restrict__ b1)
{
    const int w = (blockIdx.x * 256 + threadIdx.x) >> 5;
    const int lane = threadIdx.x & 31;
    const int half = lane >> 4;
    const int o = lane & 15;
    const int e = 2 * w + half;
    if (e >= N_EDGES) return;

    const int src = ei[e];
    const int dst = ei[N_EDGES + e];

    float s = b1[o];
    #pragma unroll
    for (int j = 0; j < F_EDGE; j++) s += ea[e*F_EDGE + j] * w1[j*HID + o];
    const float hid = fmaxf(s, 0.f);

    const __half2* P = g_P2h + (size_t)src * P2_STRIDE + o;
    float msg = __half22float2(P[8*16]).x;
    #pragma unroll
    for (int k = 0; k < 8; k++) {
        float2 f = __half22float2(P[k*16]);
        msg += __shfl_sync(0xffffffffu, hid, 2*k,   16) * f.x;
        msg += __shfl_sync(0xffffffffu, hid, 2*k+1, 16) * f.y;
    }
    atomicAdd(&g_agg2[(size_t)dst * 16 + o], msg);
}

// ---------------- fused node2 + pool: h2 = relu(h1@root2 + agg2 + bias2) -> pool atomics ----------------
// warp per 2 nodes; half-warp per node, lane = o
__global__ void __launch_bounds__(256)
node2_pool_kernel(const int* __restrict__ batch,
                  const float* __restrict__ root2, const float* __restrict__ bias2)
{
    __shared__ float sR2[32 * 16];
    __shared__ float sB2v[16];
    for (int idx = threadIdx.x; idx < 512; idx += 256) sR2[idx] = root2[idx];
    if (threadIdx.x < 16) sB2v[threadIdx.x] = bias2[threadIdx.x];
    __syncthreads();

    const int w = (blockIdx.x * 256 + threadIdx.x) >> 5;
    const int lane = threadIdx.x & 31;
    const int half = lane >> 4;
    const int o = lane & 15;
    const int n = 2 * w + half;
    if (n >= N_NODES) return;

    // cooperative load of h1 row via shfl
    const float hv0 = g_h1[(size_t)n * 32 + o];
    const float hv1 = g_h1[(size_t)n * 32 + 16 + o];

    float acc = sB2v[o] + g_agg2[(size_t)n * 16 + o];
    #pragma unroll
    for (int i = 0; i < 16; i++)
        acc += __shfl_sync(0xffffffffu, hv0, i, 16) * sR2[i*16 + o];
    #pragma unroll
    for (int i = 0; i < 16; i++)
        acc += __shfl_sync(0xffffffffu, hv1, i, 16) * sR2[(16+i)*16 + o];

    const float v = fmaxf(acc, 0.f);
    const int g = batch[n];
    atomicAdd(&g_pool[g * 16 + o], v);
    if (o == 0) atomicAdd(&g_cnt[g], 1.0f);
}

// ---------------- readout MLP ----------------
__global__ void readout_kernel(const float* __restrict__ l1w, const float* __restrict__ l1b,
                               const float* __restrict__ l2w, const float* __restrict__ l2b,
                               float* __restrict__ out)
{
    const int g = blockIdx.x * blockDim.x + threadIdx.x;
    if (g >= N_GRAPHS) return;
    const float inv = 1.0f / fmaxf(g_cnt[g], 1.0f);
    float p[16];
    #pragma unroll
    for (int o = 0; o < 16; o++) p[o] = g_pool[g * 16 + o] * inv;
    float acc = l2b[0];
    #pragma unroll
    for (int j = 0; j < 8; j++) {
        float s = l1b[j];
        #pragma unroll
        for (int o = 0; o < 16; o++) s += p[o] * l1w[o * 8 + j];
        acc += fmaxf(s, 0.f) * l2w[j];
    }
    out[g] = acc;
}

// ---------------- launch ----------------
extern "C" void kernel_launch(void* const* d_in, const int* in_sizes, int n_in,
                              void* d_out, int out_size)
{
    const float* x      = (const float*)d_in[0];
    const float* ea     = (const float*)d_in[1];
    const int*   ei     = (const int*)  d_in[2];
    const int*   batch  = (const int*)  d_in[3];
    const float* nn1_w1 = (const float*)d_in[4];
    const float* nn1_b1 = (const float*)d_in[5];
    const float* nn1_w2 = (const float*)d_in[6];
    const float* nn1_b2 = (const float*)d_in[7];
    const float* root1  = (const float*)d_in[8];
    const float* bias1  = (const float*)d_in[9];
    const float* nn2_w1 = (const float*)d_in[10];
    const float* nn2_b1 = (const float*)d_in[11];
    const float* nn2_w2 = (const float*)d_in[12];
    const float* nn2_b2 = (const float*)d_in[13];
    const float* root2  = (const float*)d_in[14];
    const float* bias2  = (const float*)d_in[15];
    const float* lin1_w = (const float*)d_in[16];
    const float* lin1_b = (const float*)d_in[17];
    const float* lin2_w = (const float*)d_in[18];
    const float* lin2_b = (const float*)d_in[19];
    float* out = (float*)d_out;

    zero_all_kernel<<<(N_NODES * 32 + 255) / 256, 256>>>();

    // ---- layer 1: 16 -> 32 ----
    p1_kernel<<<N_NODES / 16, 256>>>(x, nn1_w2, nn1_b2);
    edge1_kernel<<<(N_EDGES * 32) / 256, 256>>>(ea, ei, nn1_w1, nn1_b1);

    // ---- fused node1 + P2 precompute ----
    node1_p2_kernel<<<N_NODES / 32, 256>>>(x, root1, bias1, nn2_w2, nn2_b2);

    // ---- layer 2 edges ----
    edge2_kernel<<<(N_EDGES / 2 * 32) / 256, 256>>>(ea, ei, nn2_w1, nn2_b1);

    // ---- fused node2 + pooling ----
    node2_pool_kernel<<<(N_NODES / 2 * 32 + 255) / 256, 256>>>(batch, root2, bias2);

    // ---- readout ----
    readout_kernel<<<(N_GRAPHS + 255) / 256, 256>>>(lin1_w, lin1_b, lin2_w, lin2_b, out);
}

// round 6
// speedup vs baseline: 2.1800x; 1.0488x over previous
#include <cuda_runtime.h>
#include <cuda_fp16.h>

#define N_NODES  100000
#define N_EDGES  400000
#define N_GRAPHS 2000
#define F_EDGE   8
#define HID      16

// P stored as half pairs over h: half-col j = 2*(k*FOUT+o)+par, h = 2k+par, k=8 row = (bias, 0)
#define P1_K      9
#define P1_FOUT   32
#define P1_STRIDE (P1_K * P1_FOUT)      // 288 half2 per node (576 halves)
#define P1_COLS   (P1_STRIDE * 2)       // 576 GEMM columns
#define P2_K      9
#define P2_FOUT   16
#define P2_STRIDE (P2_K * P2_FOUT)      // 144 half2 (288 halves)
#define P2_COLS   (P2_STRIDE * 2)       // 288 GEMM columns

// ---------------- scratch ----------------
__device__ __half2 g_P1h[N_NODES * P1_STRIDE];
__device__ __half2 g_P2h[N_NODES * P2_STRIDE];
__device__ float   g_agg1[N_NODES * 32];
__device__ float   g_h1  [N_NODES * 32];
__device__ float   g_agg2[N_NODES * 16];
__device__ float   g_pool[N_GRAPHS * 16];
__device__ float   g_cnt [N_GRAPHS];

__global__ void zero_all_kernel() {
    int i = blockIdx.x * blockDim.x + threadIdx.x;
    if (i < N_NODES * 32) g_agg1[i] = 0.f;
    if (i < N_NODES * 16) g_agg2[i] = 0.f;
    if (i < N_GRAPHS * 16) g_pool[i] = 0.f;
    if (i < N_GRAPHS) g_cnt[i] = 0.f;
}

// ---------------- helpers ----------------
// Pack two floats into a 32-bit half2 register image (FULL 32 bits —
// __half2_raw(...).x is a ushort and silently truncates; that was the R5 bug).
__device__ __forceinline__ unsigned pack_half2(float a, float b) {
    __half2 h = __floats2half2_rn(a, b);
    return *reinterpret_cast<unsigned*>(&h);
}

__device__ __forceinline__ void mma16816(float c[4], const unsigned a[4], const unsigned b[2]) {
    asm volatile("mma.sync.aligned.m16n8k16.row.col.f32.f16.f16.f32 "
                 "{%0,%1,%2,%3}, {%4,%5,%6,%7}, {%8,%9}, {%0,%1,%2,%3};\n"
                 : "+f"(c[0]), "+f"(c[1]), "+f"(c[2]), "+f"(c[3])
                 : "r"(a[0]), "r"(a[1]), "r"(a[2]), "r"(a[3]),
                   "r"(b[0]), "r"(b[1]));
}

// B element for the permuted weight matrix: GEMM row i, half-col j.
// j = 2*(k*FOUT + o) + par, h = 2k + par; k==8 row is (bias, 0).
template <int FIN, int FOUT>
__device__ __forceinline__ float Belem(const float* __restrict__ w2,
                                       const float* __restrict__ b2,
                                       int i, int j) {
    const int kk  = j / (2 * FOUT);
    const int o   = (j >> 1) % FOUT;
    const int par = j & 1;
    if (kk < 8) return w2[(2*kk + par) * (FIN * FOUT) + i * FOUT + o];
    return (par == 0) ? b2[i * FOUT + o] : 0.f;
}

// ---------------- p1_tc: P1 = X[100k x 16] @ B[16 x 576], fp16 mma ----------------
// 128 threads (4 warps), 64 nodes/block; warp w covers 18 n-tiles (144 cols)
__global__ void __launch_bounds__(128)
p1_tc_kernel(const float* __restrict__ x,
             const float* __restrict__ w2, const float* __restrict__ b2)
{
    __shared__ __half sXh[64][16];

    const int tid  = threadIdx.x;
    const int lane = tid & 31;
    const int wid  = tid >> 5;
    const int nb   = blockIdx.x * 64;

    // stage X tile as fp16 (zero-fill OOB)
    for (int idx = tid; idx < 64 * 16; idx += 128) {
        const int n = nb + (idx >> 4);
        sXh[idx >> 4][idx & 15] = __float2half(n < N_NODES ? x[(size_t)n * 16 + (idx & 15)] : 0.f);
    }

    // build B fragments (18 tiles x 2 regs) once
    const int jw = wid * 144;
    const int nidx = lane >> 2;
    const int k0 = (lane & 3) * 2;
    unsigned bfrag[18][2];
    #pragma unroll
    for (int t = 0; t < 18; t++) {
        const int j = jw + t * 8 + nidx;
        bfrag[t][0] = pack_half2(Belem<16,32>(w2,b2,k0,   j), Belem<16,32>(w2,b2,k0+1, j));
        bfrag[t][1] = pack_half2(Belem<16,32>(w2,b2,k0+8, j), Belem<16,32>(w2,b2,k0+9, j));
    }
    __syncthreads();

    __half* P1 = reinterpret_cast<__half*>(g_P1h);
    const int row0 = lane >> 2;

    #pragma unroll
    for (int mt = 0; mt < 4; mt++) {
        const int m0 = mt * 16;
        unsigned a[4];
        a[0] = *(const unsigned*)&sXh[m0 + row0    ][k0    ];
        a[1] = *(const unsigned*)&sXh[m0 + row0 + 8][k0    ];
        a[2] = *(const unsigned*)&sXh[m0 + row0    ][k0 + 8];
        a[3] = *(const unsigned*)&sXh[m0 + row0 + 8][k0 + 8];

        const int nr0 = nb + m0 + row0;
        const int nr1 = nr0 + 8;
        #pragma unroll
        for (int t = 0; t < 18; t++) {
            float c[4] = {0.f, 0.f, 0.f, 0.f};
            mma16816(c, a, bfrag[t]);
            const int j0 = jw + t * 8 + (lane & 3) * 2;
            if (nr0 < N_NODES)
                *(__half2*)&P1[(size_t)nr0 * P1_COLS + j0] = __floats2half2_rn(c[0], c[1]);
            if (nr1 < N_NODES)
                *(__half2*)&P1[(size_t)nr1 * P1_COLS + j0] = __floats2half2_rn(c[2], c[3]);
        }
    }
}

// ---------------- edge1: warp per edge, lane = o ----------------
__global__ void __launch_bounds__(256)
edge1_kernel(const float* __restrict__ ea,
             const int*   __restrict__ ei,
             const float* __restrict__ w1, const float* __restrict__ b1)
{
    const int e = (blockIdx.x * 256 + threadIdx.x) >> 5;
    const int lane = threadIdx.x & 31;
    if (e >= N_EDGES) return;

    const int src = ei[e];
    const int dst = ei[N_EDGES + e];

    float hid = 0.f;
    if (lane < HID) {
        float s = b1[lane];
        #pragma unroll
        for (int j = 0; j < F_EDGE; j++) s += ea[e*F_EDGE + j] * w1[j*HID + lane];
        hid = fmaxf(s, 0.f);
    }

    const __half2* P = g_P1h + (size_t)src * P1_STRIDE + lane;
    float msg = __half22float2(P[8*32]).x;
    #pragma unroll
    for (int k = 0; k < 8; k++) {
        float2 f = __half22float2(P[k*32]);
        msg += __shfl_sync(0xffffffffu, hid, 2*k)   * f.x;
        msg += __shfl_sync(0xffffffffu, hid, 2*k+1) * f.y;
    }
    atomicAdd(&g_agg1[(size_t)dst * 32 + lane], msg);
}

// ---------------- fused node1 + P2 (tensor-core part B) ----------------
// 128 threads, 64 nodes/block. Part A: h1 scalar. Part B: P2 = H1 @ B[32 x 288] mma.
__global__ void __launch_bounds__(128)
node1_p2_tc_kernel(const float* __restrict__ x,
                   const float* __restrict__ root1, const float* __restrict__ bias1,
                   const float* __restrict__ w2,    const float* __restrict__ b2)
{
    __shared__ float  sX [64 * 16];
    __shared__ float  sR1[16 * 32];
    __shared__ float  sB1[32];
    __shared__ __half sH1[64][32];

    const int tid  = threadIdx.x;
    const int lane = tid & 31;
    const int wid  = tid >> 5;
    const int nb   = blockIdx.x * 64;

    for (int idx = tid; idx < 1024; idx += 128) {
        const int n = nb + (idx >> 4);
        sX[idx] = n < N_NODES ? x[(size_t)n * 16 + (idx & 15)] : 0.f;
    }
    for (int idx = tid; idx < 512; idx += 128) sR1[idx] = root1[idx];
    if (tid < 32) sB1[tid] = bias1[tid];

    // B fragments for P2 GEMM: 9 tiles/warp x 2 k-steps
    const int jw = wid * 72;
    const int nidx = lane >> 2;
    const int k0 = (lane & 3) * 2;
    unsigned bfrag[9][2][2];
    #pragma unroll
    for (int t = 0; t < 9; t++) {
        const int j = jw + t * 8 + nidx;
        #pragma unroll
        for (int ks = 0; ks < 2; ks++) {
            bfrag[t][ks][0] = pack_half2(Belem<32,16>(w2,b2, 16*ks + k0,     j),
                                         Belem<32,16>(w2,b2, 16*ks + k0 + 1, j));
            bfrag[t][ks][1] = pack_half2(Belem<32,16>(w2,b2, 16*ks + k0 + 8, j),
                                         Belem<32,16>(w2,b2, 16*ks + k0 + 9, j));
        }
    }
    __syncthreads();

    // part A: h1 for 64 nodes x 32 outputs
    for (int it = 0; it < 16; it++) {
        const int idx = it * 128 + tid;
        const int nl = idx >> 5;
        const int o  = idx & 31;
        const int n  = nb + nl;
        if (n < N_NODES) {
            float acc = sB1[o] + g_agg1[(size_t)n * 32 + o];
            #pragma unroll
            for (int i = 0; i < 16; i++) acc += sX[nl*16+i] * sR1[i*32+o];
            const float v = fmaxf(acc, 0.f);
            sH1[nl][o] = __float2half(v);
            g_h1[(size_t)n * 32 + o] = v;
        } else {
            sH1[nl][o] = __float2half(0.f);
        }
    }
    __syncthreads();

    // part B: mma over 4 m-tiles x 9 n-tiles x 2 k-steps
    __half* P2 = reinterpret_cast<__half*>(g_P2h);
    const int row0 = lane >> 2;

    #pragma unroll
    for (int mt = 0; mt < 4; mt++) {
        const int m0 = mt * 16;
        unsigned a[2][4];
        #pragma unroll
        for (int ks = 0; ks < 2; ks++) {
            a[ks][0] = *(const unsigned*)&sH1[m0 + row0    ][16*ks + k0    ];
            a[ks][1] = *(const unsigned*)&sH1[m0 + row0 + 8][16*ks + k0    ];
            a[ks][2] = *(const unsigned*)&sH1[m0 + row0    ][16*ks + k0 + 8];
            a[ks][3] = *(const unsigned*)&sH1[m0 + row0 + 8][16*ks + k0 + 8];
        }

        const int nr0 = nb + m0 + row0;
        const int nr1 = nr0 + 8;
        #pragma unroll
        for (int t = 0; t < 9; t++) {
            float c[4] = {0.f, 0.f, 0.f, 0.f};
            mma16816(c, a[0], bfrag[t][0]);
            mma16816(c, a[1], bfrag[t][1]);
            const int j0 = jw + t * 8 + (lane & 3) * 2;
            if (nr0 < N_NODES)
                *(__half2*)&P2[(size_t)nr0 * P2_COLS + j0] = __floats2half2_rn(c[0], c[1]);
            if (nr1 < N_NODES)
                *(__half2*)&P2[(size_t)nr1 * P2_COLS + j0] = __floats2half2_rn(c[2], c[3]);
        }
    }
}

// ---------------- edge2: half-warp per edge ----------------
__global__ void __launch_bounds__(256)
edge2_kernel(const float* __restrict__ ea,
             const int*   __restrict__ ei,
             const float* __restrict__ w1, const float* __restrict__ b1)
{
    const int w = (blockIdx.x * 256 + threadIdx.x) >> 5;
    const int lane = threadIdx.x & 31;
    const int half = lane >> 4;
    const int o = lane & 15;
    const int e = 2 * w + half;
    if (e >= N_EDGES) return;

    const int src = ei[e];
    const int dst = ei[N_EDGES + e];

    float s = b1[o];
    #pragma unroll
    for (int j = 0; j < F_EDGE; j++) s += ea[e*F_EDGE + j] * w1[j*HID + o];
    const float hid = fmaxf(s, 0.f);

    const __half2* P = g_P2h + (size_t)src * P2_STRIDE + o;
    float msg = __half22float2(P[8*16]).x;
    #pragma unroll
    for (int k = 0; k < 8; k++) {
        float2 f = __half22float2(P[k*16]);
        msg += __shfl_sync(0xffffffffu, hid, 2*k,   16) * f.x;
        msg += __shfl_sync(0xffffffffu, hid, 2*k+1, 16) * f.y;
    }
    atomicAdd(&g_agg2[(size_t)dst * 16 + o], msg);
}

// ---------------- fused node2 + pool ----------------
__global__ void __launch_bounds__(256)
node2_pool_kernel(const int* __restrict__ batch,
                  const float* __restrict__ root2, const float* __restrict__ bias2)
{
    __shared__ float sR2[32 * 16];
    __shared__ float sB2v[16];
    for (int idx = threadIdx.x; idx < 512; idx += 256) sR2[idx] = root2[idx];
    if (threadIdx.x < 16) sB2v[threadIdx.x] = bias2[threadIdx.x];
    __syncthreads();

    const int w = (blockIdx.x * 256 + threadIdx.x) >> 5;
    const int lane = threadIdx.x & 31;
    const int half = lane >> 4;
    const int o = lane & 15;
    const int n = 2 * w + half;
    if (n >= N_NODES) return;

    const float hv0 = g_h1[(size_t)n * 32 + o];
    const float hv1 = g_h1[(size_t)n * 32 + 16 + o];

    float acc = sB2v[o] + g_agg2[(size_t)n * 16 + o];
    #pragma unroll
    for (int i = 0; i < 16; i++)
        acc += __shfl_sync(0xffffffffu, hv0, i, 16) * sR2[i*16 + o];
    #pragma unroll
    for (int i = 0; i < 16; i++)
        acc += __shfl_sync(0xffffffffu, hv1, i, 16) * sR2[(16+i)*16 + o];

    const float v = fmaxf(acc, 0.f);
    const int g = batch[n];
    atomicAdd(&g_pool[g * 16 + o], v);
    if (o == 0) atomicAdd(&g_cnt[g], 1.0f);
}

// ---------------- readout MLP ----------------
__global__ void readout_kernel(const float* __restrict__ l1w, const float* __restrict__ l1b,
                               const float* __restrict__ l2w, const float* __restrict__ l2b,
                               float* __restrict__ out)
{
    const int g = blockIdx.x * blockDim.x + threadIdx.x;
    if (g >= N_GRAPHS) return;
    const float inv = 1.0f / fmaxf(g_cnt[g], 1.0f);
    float p[16];
    #pragma unroll
    for (int o = 0; o < 16; o++) p[o] = g_pool[g * 16 + o] * inv;
    float acc = l2b[0];
    #pragma unroll
    for (int j = 0; j < 8; j++) {
        float s = l1b[j];
        #pragma unroll
        for (int o = 0; o < 16; o++) s += p[o] * l1w[o * 8 + j];
        acc += fmaxf(s, 0.f) * l2w[j];
    }
    out[g] = acc;
}

// ---------------- launch ----------------
extern "C" void kernel_launch(void* const* d_in, const int* in_sizes, int n_in,
                              void* d_out, int out_size)
{
    const float* x      = (const float*)d_in[0];
    const float* ea     = (const float*)d_in[1];
    const int*   ei     = (const int*)  d_in[2];
    const int*   batch  = (const int*)  d_in[3];
    const float* nn1_w1 = (const float*)d_in[4];
    const float* nn1_b1 = (const float*)d_in[5];
    const float* nn1_w2 = (const float*)d_in[6];
    const float* nn1_b2 = (const float*)d_in[7];
    const float* root1  = (const float*)d_in[8];
    const float* bias1  = (const float*)d_in[9];
    const float* nn2_w1 = (const float*)d_in[10];
    const float* nn2_b1 = (const float*)d_in[11];
    const float* nn2_w2 = (const float*)d_in[12];
    const float* nn2_b2 = (const float*)d_in[13];
    const float* root2  = (const float*)d_in[14];
    const float* bias2  = (const float*)d_in[15];
    const float* lin1_w = (const float*)d_in[16];
    const float* lin1_b = (const float*)d_in[17];
    const float* lin2_w = (const float*)d_in[18];
    const float* lin2_b = (const float*)d_in[19];
    float* out = (float*)d_out;

    zero_all_kernel<<<(N_NODES * 32 + 255) / 256, 256>>>();

    const int nb64 = (N_NODES + 63) / 64;

    // layer 1
    p1_tc_kernel<<<nb64, 128>>>(x, nn1_w2, nn1_b2);
    edge1_kernel<<<(N_EDGES * 32) / 256, 256>>>(ea, ei, nn1_w1, nn1_b1);

    // fused node1 + P2
    node1_p2_tc_kernel<<<nb64, 128>>>(x, root1, bias1, nn2_w2, nn2_b2);

    // layer 2 edges
    edge2_kernel<<<(N_EDGES / 2 * 32) / 256, 256>>>(ea, ei, nn2_w1, nn2_b1);

    // fused node2 + pooling
    node2_pool_kernel<<<(N_NODES / 2 * 32 + 255) / 256, 256>>>(batch, root2, bias2);

    // readout
    readout_kernel<<<(N_GRAPHS + 255) / 256, 256>>>(lin1_w, lin1_b, lin2_w, lin2_b, out);
}

// round 7
// speedup vs baseline: 2.3568x; 1.0811x over previous
#include <cuda_runtime.h>
#include <cuda_fp16.h>

#define N_NODES  100000
#define N_EDGES  400000
#define N_GRAPHS 2000
#define F_EDGE   8
#define HID      16

// P stored as half pairs over h: half-col j = 2*(k*FOUT+o)+par, h = 2k+par, k=8 row = (bias, 0)
#define P1_K      9
#define P1_FOUT   32
#define P1_STRIDE (P1_K * P1_FOUT)      // 288 half2 per node (576 halves)
#define P1_COLS   (P1_STRIDE * 2)       // 576 GEMM columns
#define P2_K      9
#define P2_FOUT   16
#define P2_STRIDE (P2_K * P2_FOUT)      // 144 half2 (288 halves)
#define P2_COLS   (P2_STRIDE * 2)       // 288 GEMM columns

// fragment table sizes: p1: 4 warps x 18 tiles x 2 regs x 32 lanes
//                       p2: 4 warps x 9 tiles x 2 ks x 2 regs x 32 lanes
#define B1FRAG_N (4 * 18 * 2 * 32)      // 4608
#define B2FRAG_N (4 * 9 * 2 * 2 * 32)   // 4608

// ---------------- scratch ----------------
__device__ __half2  g_P1h[N_NODES * P1_STRIDE];
__device__ __half2  g_P2h[N_NODES * P2_STRIDE];
__device__ float    g_agg1[N_NODES * 32];
__device__ float    g_h1  [N_NODES * 32];
__device__ float    g_agg2[N_NODES * 16];
__device__ float    g_pool[N_GRAPHS * 16];
__device__ float    g_cnt [N_GRAPHS];
__device__ unsigned g_B1frag[B1FRAG_N];
__device__ unsigned g_B2frag[B2FRAG_N];

__global__ void zero_all_kernel() {
    int i = blockIdx.x * blockDim.x + threadIdx.x;
    if (i < N_NODES * 32) g_agg1[i] = 0.f;
    if (i < N_NODES * 16) g_agg2[i] = 0.f;
    if (i < N_GRAPHS * 16) g_pool[i] = 0.f;
    if (i < N_GRAPHS) g_cnt[i] = 0.f;
}

// ---------------- helpers ----------------
// Pack two floats into a 32-bit half2 register image (full 32 bits).
__device__ __forceinline__ unsigned pack_half2(float a, float b) {
    __half2 h = __floats2half2_rn(a, b);
    return *reinterpret_cast<unsigned*>(&h);
}

__device__ __forceinline__ void mma16816(float c[4], const unsigned a[4], const unsigned b[2]) {
    asm volatile("mma.sync.aligned.m16n8k16.row.col.f32.f16.f16.f32 "
                 "{%0,%1,%2,%3}, {%4,%5,%6,%7}, {%8,%9}, {%0,%1,%2,%3};\n"
                 : "+f"(c[0]), "+f"(c[1]), "+f"(c[2]), "+f"(c[3])
                 : "r"(a[0]), "r"(a[1]), "r"(a[2]), "r"(a[3]),
                   "r"(b[0]), "r"(b[1]));
}

// B element for the permuted weight matrix: GEMM row i, half-col j.
// j = 2*(k*FOUT + o) + par, h = 2k + par; k==8 row is (bias, 0).
template <int FIN, int FOUT>
__device__ __forceinline__ float Belem(const float* __restrict__ w2,
                                       const float* __restrict__ b2,
                                       int i, int j) {
    const int kk  = j / (2 * FOUT);
    const int o   = (j >> 1) % FOUT;
    const int par = j & 1;
    if (kk < 8) return w2[(2*kk + par) * (FIN * FOUT) + i * FOUT + o];
    return (par == 0) ? b2[i * FOUT + o] : 0.f;
}

// ---------------- prep: build fragment tables once ----------------
// idx decomposition matches the consuming kernels exactly.
__global__ void __launch_bounds__(256)
prep_frags_kernel(const float* __restrict__ w2_1, const float* __restrict__ b2_1,
                  const float* __restrict__ w2_2, const float* __restrict__ b2_2)
{
    const int idx = blockIdx.x * 256 + threadIdx.x;

    if (idx < B1FRAG_N) {
        // idx = ((wid*18 + t)*2 + r)*32 + lane
        const int lane = idx & 31;
        const int r    = (idx >> 5) & 1;
        const int t    = (idx >> 6) % 18;
        const int wid  = idx / (18 * 2 * 32);
        const int j    = wid * 144 + t * 8 + (lane >> 2);
        const int k0   = (lane & 3) * 2 + r * 8;
        g_B1frag[idx] = pack_half2(Belem<16,32>(w2_1, b2_1, k0,     j),
                                   Belem<16,32>(w2_1, b2_1, k0 + 1, j));
    }
    if (idx < B2FRAG_N) {
        // idx = (((wid*9 + t)*2 + ks)*2 + r)*32 + lane
        const int lane = idx & 31;
        const int r    = (idx >> 5) & 1;
        const int ks   = (idx >> 6) & 1;
        const int t    = (idx >> 7) % 9;
        const int wid  = idx / (9 * 2 * 2 * 32);
        const int j    = wid * 72 + t * 8 + (lane >> 2);
        const int k0   = 16 * ks + (lane & 3) * 2 + r * 8;
        g_B2frag[idx] = pack_half2(Belem<32,16>(w2_2, b2_2, k0,     j),
                                   Belem<32,16>(w2_2, b2_2, k0 + 1, j));
    }
}

// ---------------- p1_tc: P1 = X[100k x 16] @ B[16 x 576], fp16 mma ----------------
// 128 threads (4 warps), 64 nodes/block; warp w covers 18 n-tiles (144 cols)
__global__ void __launch_bounds__(128)
p1_tc_kernel(const float* __restrict__ x)
{
    __shared__ __half sXh[64][16];

    const int tid  = threadIdx.x;
    const int lane = tid & 31;
    const int wid  = tid >> 5;
    const int nb   = blockIdx.x * 64;

    for (int idx = tid; idx < 64 * 16; idx += 128) {
        const int n = nb + (idx >> 4);
        sXh[idx >> 4][idx & 15] = __float2half(n < N_NODES ? x[(size_t)n * 16 + (idx & 15)] : 0.f);
    }

    // coalesced fragment loads from the precomputed table
    unsigned bfrag[18][2];
    {
        const unsigned* tab = g_B1frag + (size_t)wid * 18 * 2 * 32 + lane;
        #pragma unroll
        for (int t = 0; t < 18; t++) {
            bfrag[t][0] = tab[(t * 2 + 0) * 32];
            bfrag[t][1] = tab[(t * 2 + 1) * 32];
        }
    }
    __syncthreads();

    __half* P1 = reinterpret_cast<__half*>(g_P1h);
    const int row0 = lane >> 2;
    const int k0   = (lane & 3) * 2;
    const int jw   = wid * 144;

    #pragma unroll
    for (int mt = 0; mt < 4; mt++) {
        const int m0 = mt * 16;
        unsigned a[4];
        a[0] = *(const unsigned*)&sXh[m0 + row0    ][k0    ];
        a[1] = *(const unsigned*)&sXh[m0 + row0 + 8][k0    ];
        a[2] = *(const unsigned*)&sXh[m0 + row0    ][k0 + 8];
        a[3] = *(const unsigned*)&sXh[m0 + row0 + 8][k0 + 8];

        const int nr0 = nb + m0 + row0;
        const int nr1 = nr0 + 8;
        #pragma unroll
        for (int t = 0; t < 18; t++) {
            float c[4] = {0.f, 0.f, 0.f, 0.f};
            mma16816(c, a, bfrag[t]);
            const int j0 = jw + t * 8 + (lane & 3) * 2;
            if (nr0 < N_NODES)
                *(__half2*)&P1[(size_t)nr0 * P1_COLS + j0] = __floats2half2_rn(c[0], c[1]);
            if (nr1 < N_NODES)
                *(__half2*)&P1[(size_t)nr1 * P1_COLS + j0] = __floats2half2_rn(c[2], c[3]);
        }
    }
}

// ---------------- edge1: warp per edge, lane = o ----------------
__global__ void __launch_bounds__(256)
edge1_kernel(const float* __restrict__ ea,
             const int*   __restrict__ ei,
             const float* __restrict__ w1, const float* __restrict__ b1)
{
    const int e = (blockIdx.x * 256 + threadIdx.x) >> 5;
    const int lane = threadIdx.x & 31;
    if (e >= N_EDGES) return;

    const int src = ei[e];
    const int dst = ei[N_EDGES + e];

    float hid = 0.f;
    if (lane < HID) {
        float s = b1[lane];
        #pragma unroll
        for (int j = 0; j < F_EDGE; j++) s += ea[e*F_EDGE + j] * w1[j*HID + lane];
        hid = fmaxf(s, 0.f);
    }

    const __half2* P = g_P1h + (size_t)src * P1_STRIDE + lane;
    float msg = __half22float2(P[8*32]).x;
    #pragma unroll
    for (int k = 0; k < 8; k++) {
        float2 f = __half22float2(P[k*32]);
        msg += __shfl_sync(0xffffffffu, hid, 2*k)   * f.x;
        msg += __shfl_sync(0xffffffffu, hid, 2*k+1) * f.y;
    }
    atomicAdd(&g_agg1[(size_t)dst * 32 + lane], msg);
}

// ---------------- fused node1 + P2 (tensor-core part B) ----------------
// 128 threads, 64 nodes/block. Part A: h1 scalar. Part B: P2 = H1 @ B[32 x 288] mma.
__global__ void __launch_bounds__(128)
node1_p2_tc_kernel(const float* __restrict__ x,
                   const float* __restrict__ root1, const float* __restrict__ bias1)
{
    __shared__ float  sX [64 * 16];
    __shared__ float  sR1[16 * 32];
    __shared__ float  sB1[32];
    __shared__ __half sH1[64][32];

    const int tid  = threadIdx.x;
    const int lane = tid & 31;
    const int wid  = tid >> 5;
    const int nb   = blockIdx.x * 64;

    for (int idx = tid; idx < 1024; idx += 128) {
        const int n = nb + (idx >> 4);
        sX[idx] = n < N_NODES ? x[(size_t)n * 16 + (idx & 15)] : 0.f;
    }
    for (int idx = tid; idx < 512; idx += 128) sR1[idx] = root1[idx];
    if (tid < 32) sB1[tid] = bias1[tid];

    // coalesced fragment loads
    unsigned bfrag[9][2][2];
    {
        const unsigned* tab = g_B2frag + (size_t)wid * 9 * 2 * 2 * 32 + lane;
        #pragma unroll
        for (int t = 0; t < 9; t++)
            #pragma unroll
            for (int ks = 0; ks < 2; ks++) {
                bfrag[t][ks][0] = tab[((t * 2 + ks) * 2 + 0) * 32];
                bfrag[t][ks][1] = tab[((t * 2 + ks) * 2 + 1) * 32];
            }
    }
    __syncthreads();

    // part A: h1 for 64 nodes x 32 outputs
    for (int it = 0; it < 16; it++) {
        const int idx = it * 128 + tid;
        const int nl = idx >> 5;
        const int o  = idx & 31;
        const int n  = nb + nl;
        if (n < N_NODES) {
            float acc = sB1[o] + g_agg1[(size_t)n * 32 + o];
            #pragma unroll
            for (int i = 0; i < 16; i++) acc += sX[nl*16+i] * sR1[i*32+o];
            const float v = fmaxf(acc, 0.f);
            sH1[nl][o] = __float2half(v);
            g_h1[(size_t)n * 32 + o] = v;
        } else {
            sH1[nl][o] = __float2half(0.f);
        }
    }
    __syncthreads();

    // part B: mma over 4 m-tiles x 9 n-tiles x 2 k-steps
    __half* P2 = reinterpret_cast<__half*>(g_P2h);
    const int row0 = lane >> 2;
    const int k0   = (lane & 3) * 2;
    const int jw   = wid * 72;

    #pragma unroll
    for (int mt = 0; mt < 4; mt++) {
        const int m0 = mt * 16;
        unsigned a[2][4];
        #pragma unroll
        for (int ks = 0; ks < 2; ks++) {
            a[ks][0] = *(const unsigned*)&sH1[m0 + row0    ][16*ks + k0    ];
            a[ks][1] = *(const unsigned*)&sH1[m0 + row0 + 8][16*ks + k0    ];
            a[ks][2] = *(const unsigned*)&sH1[m0 + row0    ][16*ks + k0 + 8];
            a[ks][3] = *(const unsigned*)&sH1[m0 + row0 + 8][16*ks + k0 + 8];
        }

        const int nr0 = nb + m0 + row0;
        const int nr1 = nr0 + 8;
        #pragma unroll
        for (int t = 0; t < 9; t++) {
            float c[4] = {0.f, 0.f, 0.f, 0.f};
            mma16816(c, a[0], bfrag[t][0]);
            mma16816(c, a[1], bfrag[t][1]);
            const int j0 = jw + t * 8 + (lane & 3) * 2;
            if (nr0 < N_NODES)
                *(__half2*)&P2[(size_t)nr0 * P2_COLS + j0] = __floats2half2_rn(c[0], c[1]);
            if (nr1 < N_NODES)
                *(__half2*)&P2[(size_t)nr1 * P2_COLS + j0] = __floats2half2_rn(c[2], c[3]);
        }
    }
}

// ---------------- edge2: half-warp per edge ----------------
__global__ void __launch_bounds__(256)
edge2_kernel(const float* __restrict__ ea,
             const int*   __restrict__ ei,
             const float* __restrict__ w1, const float* __restrict__ b1)
{
    const int w = (blockIdx.x * 256 + threadIdx.x) >> 5;
    const int lane = threadIdx.x & 31;
    const int half = lane >> 4;
    const int o = lane & 15;
    const int e = 2 * w + half;
    if (e >= N_EDGES) return;

    const int src = ei[e];
    const int dst = ei[N_EDGES + e];

    float s = b1[o];
    #pragma unroll
    for (int j = 0; j < F_EDGE; j++) s += ea[e*F_EDGE + j] * w1[j*HID + o];
    const float hid = fmaxf(s, 0.f);

    const __half2* P = g_P2h + (size_t)src * P2_STRIDE + o;
    float msg = __half22float2(P[8*16]).x;
    #pragma unroll
    for (int k = 0; k < 8; k++) {
        float2 f = __half22float2(P[k*16]);
        msg += __shfl_sync(0xffffffffu, hid, 2*k,   16) * f.x;
        msg += __shfl_sync(0xffffffffu, hid, 2*k+1, 16) * f.y;
    }
    atomicAdd(&g_agg2[(size_t)dst * 16 + o], msg);
}

// ---------------- fused node2 + pool ----------------
__global__ void __launch_bounds__(256)
node2_pool_kernel(const int* __restrict__ batch,
                  const float* __restrict__ root2, const float* __restrict__ bias2)
{
    __shared__ float sR2[32 * 16];
    __shared__ float sB2v[16];
    for (int idx = threadIdx.x; idx < 512; idx += 256) sR2[idx] = root2[idx];
    if (threadIdx.x < 16) sB2v[threadIdx.x] = bias2[threadIdx.x];
    __syncthreads();

    const int w = (blockIdx.x * 256 + threadIdx.x) >> 5;
    const int lane = threadIdx.x & 31;
    const int half = lane >> 4;
    const int o = lane & 15;
    const int n = 2 * w + half;
    if (n >= N_NODES) return;

    const float hv0 = g_h1[(size_t)n * 32 + o];
    const float hv1 = g_h1[(size_t)n * 32 + 16 + o];

    float acc = sB2v[o] + g_agg2[(size_t)n * 16 + o];
    #pragma unroll
    for (int i = 0; i < 16; i++)
        acc += __shfl_sync(0xffffffffu, hv0, i, 16) * sR2[i*16 + o];
    #pragma unroll
    for (int i = 0; i < 16; i++)
        acc += __shfl_sync(0xffffffffu, hv1, i, 16) * sR2[(16+i)*16 + o];

    const float v = fmaxf(acc, 0.f);
    const int g = batch[n];
    atomicAdd(&g_pool[g * 16 + o], v);
    if (o == 0) atomicAdd(&g_cnt[g], 1.0f);
}

// ---------------- readout MLP ----------------
__global__ void readout_kernel(const float* __restrict__ l1w, const float* __restrict__ l1b,
                               const float* __restrict__ l2w, const float* __restrict__ l2b,
                               float* __restrict__ out)
{
    const int g = blockIdx.x * blockDim.x + threadIdx.x;
    if (g >= N_GRAPHS) return;
    const float inv = 1.0f / fmaxf(g_cnt[g], 1.0f);
    float p[16];
    #pragma unroll
    for (int o = 0; o < 16; o++) p[o] = g_pool[g * 16 + o] * inv;
    float acc = l2b[0];
    #pragma unroll
    for (int j = 0; j < 8; j++) {
        float s = l1b[j];
        #pragma unroll
        for (int o = 0; o < 16; o++) s += p[o] * l1w[o * 8 + j];
        acc += fmaxf(s, 0.f) * l2w[j];
    }
    out[g] = acc;
}

// ---------------- launch ----------------
extern "C" void kernel_launch(void* const* d_in, const int* in_sizes, int n_in,
                              void* d_out, int out_size)
{
    const float* x      = (const float*)d_in[0];
    const float* ea     = (const float*)d_in[1];
    const int*   ei     = (const int*)  d_in[2];
    const int*   batch  = (const int*)  d_in[3];
    const float* nn1_w1 = (const float*)d_in[4];
    const float* nn1_b1 = (const float*)d_in[5];
    const float* nn1_w2 = (const float*)d_in[6];
    const float* nn1_b2 = (const float*)d_in[7];
    const float* root1  = (const float*)d_in[8];
    const float* bias1  = (const float*)d_in[9];
    const float* nn2_w1 = (const float*)d_in[10];
    const float* nn2_b1 = (const float*)d_in[11];
    const float* nn2_w2 = (const float*)d_in[12];
    const float* nn2_b2 = (const float*)d_in[13];
    const float* root2  = (const float*)d_in[14];
    const float* bias2  = (const float*)d_in[15];
    const float* lin1_w = (const float*)d_in[16];
    const float* lin1_b = (const float*)d_in[17];
    const float* lin2_w = (const float*)d_in[18];
    const float* lin2_b = (const float*)d_in[19];
    float* out = (float*)d_out;

    zero_all_kernel<<<(N_NODES * 32 + 255) / 256, 256>>>();
    prep_frags_kernel<<<(B1FRAG_N + 255) / 256, 256>>>(nn1_w2, nn1_b2, nn2_w2, nn2_b2);

    const int nb64 = (N_NODES + 63) / 64;

    // layer 1
    p1_tc_kernel<<<nb64, 128>>>(x);
    edge1_kernel<<<(N_EDGES * 32) / 256, 256>>>(ea, ei, nn1_w1, nn1_b1);

    // fused node1 + P2
    node1_p2_tc_kernel<<<nb64, 128>>>(x, root1, bias1);

    // layer 2 edges
    edge2_kernel<<<(N_EDGES / 2 * 32) / 256, 256>>>(ea, ei, nn2_w1, nn2_b1);

    // fused node2 + pooling
    node2_pool_kernel<<<(N_NODES / 2 * 32 + 255) / 256, 256>>>(batch, root2, bias2);

    // readout
    readout_kernel<<<(N_GRAPHS + 255) / 256, 256>>>(lin1_w, lin1_b, lin2_w, lin2_b, out);
}

// round 8
// speedup vs baseline: 4.5279x; 1.9212x over previous
#include <cuda_runtime.h>
#include <cuda_fp16.h>

#define N_NODES  100000
#define N_EDGES  400000
#define N_GRAPHS 2000
#define F_EDGE   8
#define HID      16

// z-GEMM B-fragment tables.
// Layer1: msg[E x 32] = Z1[E x 272] @ B1[272 x 32];  z1[c]=hid[c>>4]*x[c&15] (c<256), =x[c-256] (bias)
// Layer2: msg[E x 16] = Z2[E x 544] @ B2[544 x 16];  z2[c]=hid[c>>5]*h1[c&31] (c<512), =h1[c-512] (bias)
#define B1_TILES 4
#define B1_KS    17
#define B2_TILES 2
#define B2_KS    34
#define B1TAB_N (B1_TILES * B1_KS * 2 * 32)   // 4352
#define B2TAB_N (B2_TILES * B2_KS * 2 * 32)   // 4352

// ---------------- scratch ----------------
__device__ float    g_agg1[N_NODES * 32];
__device__ float    g_agg2[N_NODES * 16];
__device__ float    g_pool[N_GRAPHS * 16];
__device__ float    g_cnt [N_GRAPHS];
__device__ unsigned g_xh2 [N_NODES * 8];    // x rows as 8 packed half2
__device__ unsigned g_h1h2[N_NODES * 16];   // h1 rows as 16 packed half2
__device__ unsigned g_B1tab[B1TAB_N];
__device__ unsigned g_B2tab[B2TAB_N];

__global__ void zero_all_kernel() {
    int i = blockIdx.x * blockDim.x + threadIdx.x;
    if (i < N_NODES * 32) g_agg1[i] = 0.f;
    if (i < N_NODES * 16) g_agg2[i] = 0.f;
    if (i < N_GRAPHS * 16) g_pool[i] = 0.f;
    if (i < N_GRAPHS) g_cnt[i] = 0.f;
}

// ---------------- helpers ----------------
__device__ __forceinline__ unsigned pack_half2(float a, float b) {
    __half2 h = __floats2half2_rn(a, b);
    return *reinterpret_cast<unsigned*>(&h);
}
__device__ __forceinline__ unsigned hmul2u(unsigned a, unsigned b) {
    __half2 r = __hmul2(*reinterpret_cast<__half2*>(&a), *reinterpret_cast<__half2*>(&b));
    return *reinterpret_cast<unsigned*>(&r);
}
__device__ __forceinline__ void mma16816(float c[4], const unsigned a[4], const unsigned b[2]) {
    asm volatile("mma.sync.aligned.m16n8k16.row.col.f32.f16.f16.f32 "
                 "{%0,%1,%2,%3}, {%4,%5,%6,%7}, {%8,%9}, {%0,%1,%2,%3};\n"
                 : "+f"(c[0]), "+f"(c[1]), "+f"(c[2]), "+f"(c[3])
                 : "r"(a[0]), "r"(a[1]), "r"(a[2]), "r"(a[3]),
                   "r"(b[0]), "r"(b[1]));
}

// ---------------- prep: B tables + x fp16 conversion ----------------
// Fragment convention (verified in R6/R7): for a (tile t, k-step ks):
//   reg r holds B[16ks + (lane&3)*2 + 8r + {0,1}, col = t*8 + (lane>>2)]
__global__ void __launch_bounds__(256)
prep_tabs_kernel(const float* __restrict__ w2_1, const float* __restrict__ b2_1,
                 const float* __restrict__ w2_2, const float* __restrict__ b2_2)
{
    const int idx = blockIdx.x * 256 + threadIdx.x;
    if (idx < B1TAB_N) {
        const int lane = idx & 31;
        const int r    = (idx >> 5) & 1;
        const int ks   = (idx >> 6) % B1_KS;
        const int t    = idx / (B1_KS * 2 * 32);
        const int o    = t * 8 + (lane >> 2);
        const int c    = 16 * ks + (lane & 3) * 2 + r * 8;  // even
        float v0, v1;
        if (c < 256) { const int h = c >> 4, i = c & 15;
            v0 = w2_1[h * 512 + i * 32 + o]; v1 = w2_1[h * 512 + (i + 1) * 32 + o];
        } else { const int i = c - 256;
            v0 = b2_1[i * 32 + o]; v1 = b2_1[(i + 1) * 32 + o];
        }
        g_B1tab[idx] = pack_half2(v0, v1);
    }
    if (idx < B2TAB_N) {
        const int lane = idx & 31;
        const int r    = (idx >> 5) & 1;
        const int ks   = (idx >> 6) % B2_KS;
        const int t    = idx / (B2_KS * 2 * 32);
        const int o    = t * 8 + (lane >> 2);
        const int c    = 16 * ks + (lane & 3) * 2 + r * 8;  // even
        float v0, v1;
        if (c < 512) { const int h = c >> 5, i = c & 31;
            v0 = w2_2[h * 512 + i * 16 + o]; v1 = w2_2[h * 512 + (i + 1) * 16 + o];
        } else { const int i = c - 512;
            v0 = b2_2[i * 16 + o]; v1 = b2_2[(i + 1) * 16 + o];
        }
        g_B2tab[idx] = pack_half2(v0, v1);
    }
}

__global__ void __launch_bounds__(256)
prep_xh2_kernel(const float* __restrict__ x)
{
    const int p = blockIdx.x * 256 + threadIdx.x;
    if (p < N_NODES * 8)
        g_xh2[p] = pack_half2(x[2 * p], x[2 * p + 1]);
}

// ---------------- edge1_z: warp per 16-edge tile, z1 built in registers ----------------
__global__ void __launch_bounds__(256)
edge1_z_kernel(const float* __restrict__ ea,
               const int*   __restrict__ ei,
               const float* __restrict__ w1, const float* __restrict__ b1)
{
    __shared__ unsigned sBt[B1TAB_N];                 // 17 KB
    __shared__ float    sW1[F_EDGE * HID];
    __shared__ float    sB1v[HID];
    __shared__ __align__(16) unsigned sXH[8][16][12]; // x pairs per warp (stride 12 = bank-safe)
    __shared__ unsigned sH2[8][16][17];               // hid dup-pairs per warp

    const int tid  = threadIdx.x;
    const int lane = tid & 31;
    const int wid  = tid >> 5;

    for (int i = tid; i < B1TAB_N; i += 256) sBt[i] = g_B1tab[i];
    if (tid < F_EDGE * HID) sW1[tid] = w1[tid];
    if (tid < HID) sB1v[tid] = b1[tid];
    __syncthreads();

    const int e0 = (blockIdx.x * 8 + wid) * 16;

    // src indices (lanes 0..15)
    int src_reg = 0;
    if (lane < 16) src_reg = ei[e0 + lane];

    // x gather: 2 lanes per edge, 16B each
    {
        const int e = lane >> 1, part = lane & 1;
        const int s = __shfl_sync(0xffffffffu, src_reg, e);
        const uint4 v = *(const uint4*)(g_xh2 + (size_t)s * 8 + part * 4);
        *(uint4*)&sXH[wid][e][part * 4] = v;
    }
    // hid: lane handles edge lane&15, h-range (lane>>4)*8
    {
        const int e = lane & 15, hh = (lane >> 4) * 8;
        const float4 v0 = *(const float4*)(ea + (size_t)(e0 + e) * 8);
        const float4 v1 = *(const float4*)(ea + (size_t)(e0 + e) * 8 + 4);
        const float eav[8] = {v0.x, v0.y, v0.z, v0.w, v1.x, v1.y, v1.z, v1.w};
        #pragma unroll
        for (int m = 0; m < 8; m++) {
            const int h = hh + m;
            float s = sB1v[h];
            #pragma unroll
            for (int j = 0; j < F_EDGE; j++) s += eav[j] * sW1[j * HID + h];
            const float v = fmaxf(s, 0.f);
            sH2[wid][e][h] = pack_half2(v, v);
        }
    }
    __syncwarp();

    const int row0 = lane >> 2, row1 = row0 + 8;
    const int k0   = (lane & 3) * 2;
    const int p    = k0 >> 1;

    const unsigned xp00 = sXH[wid][row0][p], xp01 = sXH[wid][row0][p + 4];
    const unsigned xp10 = sXH[wid][row1][p], xp11 = sXH[wid][row1][p + 4];

    float acc[4][4] = {};
    #pragma unroll
    for (int ks = 0; ks < 16; ks++) {
        const unsigned h20 = sH2[wid][row0][ks];
        const unsigned h21 = sH2[wid][row1][ks];
        const unsigned a[4] = {hmul2u(h20, xp00), hmul2u(h21, xp10),
                               hmul2u(h20, xp01), hmul2u(h21, xp11)};
        #pragma unroll
        for (int t = 0; t < 4; t++) {
            const unsigned* bp = &sBt[((t * B1_KS + ks) * 2) * 32 + lane];
            const unsigned b[2] = {bp[0], bp[32]};
            mma16816(acc[t], a, b);
        }
    }
    {   // bias k-step (z = x)
        const unsigned a[4] = {xp00, xp10, xp01, xp11};
        #pragma unroll
        for (int t = 0; t < 4; t++) {
            const unsigned* bp = &sBt[((t * B1_KS + 16) * 2) * 32 + lane];
            const unsigned b[2] = {bp[0], bp[32]};
            mma16816(acc[t], a, b);
        }
    }

    const int d0 = ei[N_EDGES + e0 + row0];
    const int d1 = ei[N_EDGES + e0 + row1];
    #pragma unroll
    for (int t = 0; t < 4; t++) {
        const int o = t * 8 + k0;
        atomicAdd(&g_agg1[(size_t)d0 * 32 + o],     acc[t][0]);
        atomicAdd(&g_agg1[(size_t)d0 * 32 + o + 1], acc[t][1]);
        atomicAdd(&g_agg1[(size_t)d1 * 32 + o],     acc[t][2]);
        atomicAdd(&g_agg1[(size_t)d1 * 32 + o + 1], acc[t][3]);
    }
}

// ---------------- node1: h1 = relu(x@root1 + agg1 + bias1) -> fp16 pairs ----------------
// block covers 16 nodes; thread = (node, output-pair)
__global__ void __launch_bounds__(256)
node1_kernel(const float* __restrict__ x,
             const float* __restrict__ root1, const float* __restrict__ bias1)
{
    __shared__ float sR1[16 * 32];
    __shared__ float sB1[32];
    __shared__ float sX[16][17];

    const int tid = threadIdx.x;
    const int nb  = blockIdx.x * 16;

    for (int i = tid; i < 512; i += 256) sR1[i] = root1[i];
    if (tid < 32) sB1[tid] = bias1[tid];
    if (tid < 256) {
        const int nl = tid >> 4, i = tid & 15;
        sX[nl][i] = x[(size_t)(nb + nl) * 16 + i];
    }
    __syncthreads();

    const int nl = tid >> 4;       // local node
    const int pr = tid & 15;       // output pair
    const int n  = nb + nl;
    const int o0 = 2 * pr, o1 = o0 + 1;

    float a0 = sB1[o0] + g_agg1[(size_t)n * 32 + o0];
    float a1 = sB1[o1] + g_agg1[(size_t)n * 32 + o1];
    #pragma unroll
    for (int i = 0; i < 16; i++) {
        const float xi = sX[nl][i];
        a0 += xi * sR1[i * 32 + o0];
        a1 += xi * sR1[i * 32 + o1];
    }
    g_h1h2[(size_t)n * 16 + pr] = pack_half2(fmaxf(a0, 0.f), fmaxf(a1, 0.f));
}

// ---------------- edge2_z: warp per 16-edge tile ----------------
__global__ void __launch_bounds__(256)
edge2_z_kernel(const float* __restrict__ ea,
               const int*   __restrict__ ei,
               const float* __restrict__ w1, const float* __restrict__ b1)
{
    __shared__ unsigned sBt[B2TAB_N];                 // 17 KB
    __shared__ float    sW1[F_EDGE * HID];
    __shared__ float    sB1v[HID];
    __shared__ __align__(16) unsigned sHH[8][16][20]; // h1 pairs per warp (stride 20 = aligned+bank-safe)
    __shared__ unsigned sH2[8][16][17];               // hid dup-pairs

    const int tid  = threadIdx.x;
    const int lane = tid & 31;
    const int wid  = tid >> 5;

    for (int i = tid; i < B2TAB_N; i += 256) sBt[i] = g_B2tab[i];
    if (tid < F_EDGE * HID) sW1[tid] = w1[tid];
    if (tid < HID) sB1v[tid] = b1[tid];
    __syncthreads();

    const int e0 = (blockIdx.x * 8 + wid) * 16;

    int src_reg = 0;
    if (lane < 16) src_reg = ei[e0 + lane];

    // h1 gather: 2 lanes per edge, 32B each (2 x uint4)
    {
        const int e = lane >> 1, part = lane & 1;
        const int s = __shfl_sync(0xffffffffu, src_reg, e);
        const uint4 va = *(const uint4*)(g_h1h2 + (size_t)s * 16 + part * 8);
        const uint4 vb = *(const uint4*)(g_h1h2 + (size_t)s * 16 + part * 8 + 4);
        *(uint4*)&sHH[wid][e][part * 8]     = va;
        *(uint4*)&sHH[wid][e][part * 8 + 4] = vb;
    }
    // hid
    {
        const int e = lane & 15, hh = (lane >> 4) * 8;
        const float4 v0 = *(const float4*)(ea + (size_t)(e0 + e) * 8);
        const float4 v1 = *(const float4*)(ea + (size_t)(e0 + e) * 8 + 4);
        const float eav[8] = {v0.x, v0.y, v0.z, v0.w, v1.x, v1.y, v1.z, v1.w};
        #pragma unroll
        for (int m = 0; m < 8; m++) {
            const int h = hh + m;
            float s = sB1v[h];
            #pragma unroll
            for (int j = 0; j < F_EDGE; j++) s += eav[j] * sW1[j * HID + h];
            const float v = fmaxf(s, 0.f);
            sH2[wid][e][h] = pack_half2(v, v);
        }
    }
    __syncwarp();

    const int row0 = lane >> 2, row1 = row0 + 8;
    const int k0   = (lane & 3) * 2;
    const int p    = k0 >> 1;

    // h1 pairs used by this thread: {p, p+4} (i<16 half), {p+8, p+12} (i>=16 half)
    const unsigned x0[4] = {sHH[wid][row0][p], sHH[wid][row0][p + 4],
                            sHH[wid][row0][p + 8], sHH[wid][row0][p + 12]};
    const unsigned x1[4] = {sHH[wid][row1][p], sHH[wid][row1][p + 4],
                            sHH[wid][row1][p + 8], sHH[wid][row1][p + 12]};

    float acc[2][4] = {};
    #pragma unroll
    for (int m = 0; m < 16; m++) {
        const unsigned h20 = sH2[wid][row0][m];
        const unsigned h21 = sH2[wid][row1][m];
        {   // ks = 2m  (i in [0,16))
            const unsigned a[4] = {hmul2u(h20, x0[0]), hmul2u(h21, x1[0]),
                                   hmul2u(h20, x0[1]), hmul2u(h21, x1[1])};
            #pragma unroll
            for (int t = 0; t < 2; t++) {
                const unsigned* bp = &sBt[((t * B2_KS + 2 * m) * 2) * 32 + lane];
                const unsigned b[2] = {bp[0], bp[32]};
                mma16816(acc[t], a, b);
            }
        }
        {   // ks = 2m+1 (i in [16,32))
            const unsigned a[4] = {hmul2u(h20, x0[2]), hmul2u(h21, x1[2]),
                                   hmul2u(h20, x0[3]), hmul2u(h21, x1[3])};
            #pragma unroll
            for (int t = 0; t < 2; t++) {
                const unsigned* bp = &sBt[((t * B2_KS + 2 * m + 1) * 2) * 32 + lane];
                const unsigned b[2] = {bp[0], bp[32]};
                mma16816(acc[t], a, b);
            }
        }
    }
    {   // bias ks=32 (z = h1[0..16))
        const unsigned a[4] = {x0[0], x1[0], x0[1], x1[1]};
        #pragma unroll
        for (int t = 0; t < 2; t++) {
            const unsigned* bp = &sBt[((t * B2_KS + 32) * 2) * 32 + lane];
            const unsigned b[2] = {bp[0], bp[32]};
            mma16816(acc[t], a, b);
        }
    }
    {   // bias ks=33 (z = h1[16..32))
        const unsigned a[4] = {x0[2], x1[2], x0[3], x1[3]};
        #pragma unroll
        for (int t = 0; t < 2; t++) {
            const unsigned* bp = &sBt[((t * B2_KS + 33) * 2) * 32 + lane];
            const unsigned b[2] = {bp[0], bp[32]};
            mma16816(acc[t], a, b);
        }
    }

    const int d0 = ei[N_EDGES + e0 + row0];
    const int d1 = ei[N_EDGES + e0 + row1];
    #pragma unroll
    for (int t = 0; t < 2; t++) {
        const int o = t * 8 + k0;
        atomicAdd(&g_agg2[(size_t)d0 * 16 + o],     acc[t][0]);
        atomicAdd(&g_agg2[(size_t)d0 * 16 + o + 1], acc[t][1]);
        atomicAdd(&g_agg2[(size_t)d1 * 16 + o],     acc[t][2]);
        atomicAdd(&g_agg2[(size_t)d1 * 16 + o + 1], acc[t][3]);
    }
}

// ---------------- fused node2 + pool (h1 from fp16 pairs) ----------------
__global__ void __launch_bounds__(256)
node2_pool_kernel(const int* __restrict__ batch,
                  const float* __restrict__ root2, const float* __restrict__ bias2)
{
    __shared__ float sR2[32 * 16];
    __shared__ float sB2v[16];
    for (int idx = threadIdx.x; idx < 512; idx += 256) sR2[idx] = root2[idx];
    if (threadIdx.x < 16) sB2v[threadIdx.x] = bias2[threadIdx.x];
    __syncthreads();

    const int w = (blockIdx.x * 256 + threadIdx.x) >> 5;
    const int lane = threadIdx.x & 31;
    const int half = lane >> 4;
    const int o = lane & 15;
    const int n = 2 * w + half;
    if (n >= N_NODES) return;

    const unsigned hp = g_h1h2[(size_t)n * 16 + o];   // pair (2o, 2o+1)

    float acc = sB2v[o] + g_agg2[(size_t)n * 16 + o];
    #pragma unroll
    for (int i = 0; i < 16; i++) {
        const unsigned pi = __shfl_sync(0xffffffffu, hp, i, 16);
        const float2 f = __half22float2(*reinterpret_cast<const __half2*>(&pi));
        acc += f.x * sR2[(2 * i) * 16 + o] + f.y * sR2[(2 * i + 1) * 16 + o];
    }

    const float v = fmaxf(acc, 0.f);
    const int g = batch[n];
    atomicAdd(&g_pool[g * 16 + o], v);
    if (o == 0) atomicAdd(&g_cnt[g], 1.0f);
}

// ---------------- readout MLP ----------------
__global__ void readout_kernel(const float* __restrict__ l1w, const float* __restrict__ l1b,
                               const float* __restrict__ l2w, const float* __restrict__ l2b,
                               float* __restrict__ out)
{
    const int g = blockIdx.x * blockDim.x + threadIdx.x;
    if (g >= N_GRAPHS) return;
    const float inv = 1.0f / fmaxf(g_cnt[g], 1.0f);
    float p[16];
    #pragma unroll
    for (int o = 0; o < 16; o++) p[o] = g_pool[g * 16 + o] * inv;
    float acc = l2b[0];
    #pragma unroll
    for (int j = 0; j < 8; j++) {
        float s = l1b[j];
        #pragma unroll
        for (int o = 0; o < 16; o++) s += p[o] * l1w[o * 8 + j];
        acc += fmaxf(s, 0.f) * l2w[j];
    }
    out[g] = acc;
}

// ---------------- launch ----------------
extern "C" void kernel_launch(void* const* d_in, const int* in_sizes, int n_in,
                              void* d_out, int out_size)
{
    const float* x      = (const float*)d_in[0];
    const float* ea     = (const float*)d_in[1];
    const int*   ei     = (const int*)  d_in[2];
    const int*   batch  = (const int*)  d_in[3];
    const float* nn1_w1 = (const float*)d_in[4];
    const float* nn1_b1 = (const float*)d_in[5];
    const float* nn1_w2 = (const float*)d_in[6];
    const float* nn1_b2 = (const float*)d_in[7];
    const float* root1  = (const float*)d_in[8];
    const float* bias1  = (const float*)d_in[9];
    const float* nn2_w1 = (const float*)d_in[10];
    const float* nn2_b1 = (const float*)d_in[11];
    const float* nn2_w2 = (const float*)d_in[12];
    const float* nn2_b2 = (const float*)d_in[13];
    const float* root2  = (const float*)d_in[14];
    const float* bias2  = (const float*)d_in[15];
    const float* lin1_w = (const float*)d_in[16];
    const float* lin1_b = (const float*)d_in[17];
    const float* lin2_w = (const float*)d_in[18];
    const float* lin2_b = (const float*)d_in[19];
    float* out = (float*)d_out;

    zero_all_kernel<<<(N_NODES * 32 + 255) / 256, 256>>>();
    prep_tabs_kernel<<<(B1TAB_N + 255) / 256, 256>>>(nn1_w2, nn1_b2, nn2_w2, nn2_b2);
    prep_xh2_kernel<<<(N_NODES * 8 + 255) / 256, 256>>>(x);

    // layer 1: 25000 tiles of 16 edges, 8 warps/block
    edge1_z_kernel<<<N_EDGES / 16 / 8, 256>>>(ea, ei, nn1_w1, nn1_b1);

    // node update 1 -> fp16 h1
    node1_kernel<<<N_NODES / 16, 256>>>(x, root1, bias1);

    // layer 2
    edge2_z_kernel<<<N_EDGES / 16 / 8, 256>>>(ea, ei, nn2_w1, nn2_b1);

    // node update 2 + pooling
    node2_pool_kernel<<<(N_NODES / 2 * 32 + 255) / 256, 256>>>(batch, root2, bias2);

    // readout
    readout_kernel<<<(N_GRAPHS + 255) / 256, 256>>>(lin1_w, lin1_b, lin2_w, lin2_b, out);
}

// round 10
// speedup vs baseline: 5.4580x; 1.2054x over previous
#include <cuda_runtime.h>
#include <cuda_fp16.h>

#define N_NODES  100000
#define N_EDGES  400000
#define N_GRAPHS 2000
#define F_EDGE   8
#define HID      16

// z-GEMM B-fragment tables (pair-adjacent layout for LDS.64):
//   idx = ((t*KS + ks)*32 + lane)*2 + r
// Layer1: msg[E x 32] = Z1[E x 272] @ B1[272 x 32];  z1[c]=hid[c>>4]*x[c&15] (c<256), =x[c-256]
// Layer2: msg[E x 16] = Z2[E x 544] @ B2[544 x 16];  z2[c]=hid[c>>5]*h1[c&31] (c<512), =h1[c-512]
#define B1_TILES 4
#define B1_KS    17
#define B2_TILES 2
#define B2_KS    34
#define B1TAB_N (B1_TILES * B1_KS * 2 * 32)   // 4352
#define B2TAB_N (B2_TILES * B2_KS * 2 * 32)   // 4352

#define WTILES1 (N_EDGES / 32)                // 12500 warp-tiles of 32 edges

// edge2 dynamic smem layout (bytes)
#define E2_OFF_BT   0
#define E2_OFF_W1   (E2_OFF_BT + B2TAB_N * 4)            // 17408
#define E2_OFF_B1   (E2_OFF_W1 + F_EDGE * HID * 4)       // 17920
#define E2_OFF_HH   (E2_OFF_B1 + 64)                     // 17984 (16B aligned)
#define E2_OFF_H2   (E2_OFF_HH + 8 * 32 * 20 * 4)        // 38464
#define E2_SMEM     (E2_OFF_H2 + 8 * 32 * 17 * 4)        // 55872

// ---------------- scratch ----------------
__device__ float    g_agg1[N_NODES * 32];
__device__ float    g_agg2[N_NODES * 16];
__device__ float    g_pool[N_GRAPHS * 16];
__device__ float    g_cnt [N_GRAPHS];
__device__ unsigned g_xh2 [N_NODES * 8];    // x rows as 8 packed half2
__device__ unsigned g_h1h2[N_NODES * 16];   // h1 rows as 16 packed half2
__device__ unsigned g_B1tab[B1TAB_N];
__device__ unsigned g_B2tab[B2TAB_N];

__global__ void zero_all_kernel() {
    int i = blockIdx.x * blockDim.x + threadIdx.x;
    if (i < N_NODES * 32) g_agg1[i] = 0.f;
    if (i < N_NODES * 16) g_agg2[i] = 0.f;
    if (i < N_GRAPHS * 16) g_pool[i] = 0.f;
    if (i < N_GRAPHS) g_cnt[i] = 0.f;
}

// ---------------- helpers ----------------
__device__ __forceinline__ unsigned pack_half2(float a, float b) {
    __half2 h = __floats2half2_rn(a, b);
    return *reinterpret_cast<unsigned*>(&h);
}
__device__ __forceinline__ unsigned hmul2u(unsigned a, unsigned b) {
    __half2 r = __hmul2(*reinterpret_cast<__half2*>(&a), *reinterpret_cast<__half2*>(&b));
    return *reinterpret_cast<unsigned*>(&r);
}
__device__ __forceinline__ void mma16816(float c[4], const unsigned a[4], const unsigned b[2]) {
    asm volatile("mma.sync.aligned.m16n8k16.row.col.f32.f16.f16.f32 "
                 "{%0,%1,%2,%3}, {%4,%5,%6,%7}, {%8,%9}, {%0,%1,%2,%3};\n"
                 : "+f"(c[0]), "+f"(c[1]), "+f"(c[2]), "+f"(c[3])
                 : "r"(a[0]), "r"(a[1]), "r"(a[2]), "r"(a[3]),
                   "r"(b[0]), "r"(b[1]));
}
__device__ __forceinline__ void red_v2(float* p, float a, float b) {
    asm volatile("red.global.add.v2.f32 [%0], {%1, %2};" :: "l"(p), "f"(a), "f"(b) : "memory");
}

// ---------------- prep: B tables + x fp16 conversion ----------------
// Fragment convention (R6-verified): (tile t, k-step ks), reg r holds
//   B[16ks + (lane&3)*2 + 8r + {0,1}, col = t*8 + (lane>>2)]
__global__ void __launch_bounds__(256)
prep_tabs_kernel(const float* __restrict__ w2_1, const float* __restrict__ b2_1,
                 const float* __restrict__ w2_2, const float* __restrict__ b2_2)
{
    const int idx = blockIdx.x * 256 + threadIdx.x;
    if (idx < B1TAB_N) {
        const int r    = idx & 1;
        const int lane = (idx >> 1) & 31;
        const int ks   = (idx >> 6) % B1_KS;
        const int t    = idx / (B1_KS * 2 * 32);
        const int o    = t * 8 + (lane >> 2);
        const int c    = 16 * ks + (lane & 3) * 2 + r * 8;  // even
        float v0, v1;
        if (c < 256) { const int h = c >> 4, i = c & 15;
            v0 = w2_1[h * 512 + i * 32 + o]; v1 = w2_1[h * 512 + (i + 1) * 32 + o];
        } else { const int i = c - 256;
            v0 = b2_1[i * 32 + o]; v1 = b2_1[(i + 1) * 32 + o];
        }
        g_B1tab[idx] = pack_half2(v0, v1);
    }
    if (idx < B2TAB_N) {
        const int r    = idx & 1;
        const int lane = (idx >> 1) & 31;
        const int ks   = (idx >> 6) % B2_KS;
        const int t    = idx / (B2_KS * 2 * 32);
        const int o    = t * 8 + (lane >> 2);
        const int c    = 16 * ks + (lane & 3) * 2 + r * 8;  // even
        float v0, v1;
        if (c < 512) { const int h = c >> 5, i = c & 31;
            v0 = w2_2[h * 512 + i * 16 + o]; v1 = w2_2[h * 512 + (i + 1) * 16 + o];
        } else { const int i = c - 512;
            v0 = b2_2[i * 16 + o]; v1 = b2_2[(i + 1) * 16 + o];
        }
        g_B2tab[idx] = pack_half2(v0, v1);
    }
}

__global__ void __launch_bounds__(256)
prep_xh2_kernel(const float* __restrict__ x)
{
    const int p = blockIdx.x * 256 + threadIdx.x;
    if (p < N_NODES * 8)
        g_xh2[p] = pack_half2(x[2 * p], x[2 * p + 1]);
}

// ---------------- edge1_z: warp per 32-edge tile (2 m-tiles share B regs) ----------------
__global__ void __launch_bounds__(256)
edge1_z_kernel(const float* __restrict__ ea,
               const int*   __restrict__ ei,
               const float* __restrict__ w1, const float* __restrict__ b1)
{
    __shared__ unsigned sBt[B1TAB_N];                 // 17 KB
    __shared__ float    sW1[F_EDGE * HID];
    __shared__ float    sB1v[HID];
    __shared__ __align__(16) unsigned sXH[8][32][12]; // x pairs (8/edge) 12 KB
    __shared__ unsigned sH2[8][32][17];               // hid dup-pairs   17 KB

    const int tid  = threadIdx.x;
    const int lane = tid & 31;
    const int wid  = tid >> 5;

    for (int i = tid; i < B1TAB_N; i += 256) sBt[i] = g_B1tab[i];
    if (tid < F_EDGE * HID) sW1[tid] = w1[tid];
    if (tid < HID) sB1v[tid] = b1[tid];
    __syncthreads();

    const int wtile = blockIdx.x * 8 + wid;
    if (wtile >= WTILES1) return;
    const int e0 = wtile * 32;

    const int src_reg = ei[e0 + lane];
    const int dst_reg = ei[N_EDGES + e0 + lane];

    // x gather: 2 lanes per edge, 2 iterations
    #pragma unroll
    for (int it = 0; it < 2; it++) {
        const int e = it * 16 + (lane >> 1), part = lane & 1;
        const int s = __shfl_sync(0xffffffffu, src_reg, e);
        const uint4 v = *(const uint4*)(g_xh2 + (size_t)s * 8 + part * 4);
        *(uint4*)&sXH[wid][e][part * 4] = v;
    }
    // hid: each lane = one edge, all 16 h
    {
        const float4 v0 = *(const float4*)(ea + (size_t)(e0 + lane) * 8);
        const float4 v1 = *(const float4*)(ea + (size_t)(e0 + lane) * 8 + 4);
        const float eav[8] = {v0.x, v0.y, v0.z, v0.w, v1.x, v1.y, v1.z, v1.w};
        #pragma unroll
        for (int h = 0; h < HID; h++) {
            float s = sB1v[h];
            #pragma unroll
            for (int j = 0; j < F_EDGE; j++) s += eav[j] * sW1[j * HID + h];
            const float v = fmaxf(s, 0.f);
            sH2[wid][lane][h] = pack_half2(v, v);
        }
    }
    __syncwarp();

    const int row0 = lane >> 2, row1 = row0 + 8;
    const int ra0 = row0, ra1 = row1;           // m-tile 0 edges
    const int rb0 = row0 + 16, rb1 = row1 + 16; // m-tile 1 edges
    const int k0 = (lane & 3) * 2;
    const int p  = k0 >> 1;

    const unsigned xa0 = sXH[wid][ra0][p], xa1 = sXH[wid][ra0][p + 4];
    const unsigned xa2 = sXH[wid][ra1][p], xa3 = sXH[wid][ra1][p + 4];
    const unsigned xb0 = sXH[wid][rb0][p], xb1 = sXH[wid][rb0][p + 4];
    const unsigned xb2 = sXH[wid][rb1][p], xb3 = sXH[wid][rb1][p + 4];

    float accA[4][4] = {}, accB[4][4] = {};
    #pragma unroll
    for (int ks = 0; ks < 16; ks++) {
        const unsigned ha0 = sH2[wid][ra0][ks], ha1 = sH2[wid][ra1][ks];
        const unsigned hb0 = sH2[wid][rb0][ks], hb1 = sH2[wid][rb1][ks];
        const unsigned aA[4] = {hmul2u(ha0, xa0), hmul2u(ha1, xa2),
                                hmul2u(ha0, xa1), hmul2u(ha1, xa3)};
        const unsigned aB[4] = {hmul2u(hb0, xb0), hmul2u(hb1, xb2),
                                hmul2u(hb0, xb1), hmul2u(hb1, xb3)};
        #pragma unroll
        for (int t = 0; t < 4; t++) {
            const uint2 bv = *(const uint2*)&sBt[((t * B1_KS + ks) * 32 + lane) * 2];
            const unsigned b[2] = {bv.x, bv.y};
            mma16816(accA[t], aA, b);
            mma16816(accB[t], aB, b);
        }
    }
    {   // bias k-step (z = x)
        const unsigned aA[4] = {xa0, xa2, xa1, xa3};
        const unsigned aB[4] = {xb0, xb2, xb1, xb3};
        #pragma unroll
        for (int t = 0; t < 4; t++) {
            const uint2 bv = *(const uint2*)&sBt[((t * B1_KS + 16) * 32 + lane) * 2];
            const unsigned b[2] = {bv.x, bv.y};
            mma16816(accA[t], aA, b);
            mma16816(accB[t], aB, b);
        }
    }

    const int dA0 = __shfl_sync(0xffffffffu, dst_reg, ra0);
    const int dA1 = __shfl_sync(0xffffffffu, dst_reg, ra1);
    const int dB0 = __shfl_sync(0xffffffffu, dst_reg, rb0);
    const int dB1 = __shfl_sync(0xffffffffu, dst_reg, rb1);
    #pragma unroll
    for (int t = 0; t < 4; t++) {
        const int o = t * 8 + k0;
        red_v2(&g_agg1[(size_t)dA0 * 32 + o], accA[t][0], accA[t][1]);
        red_v2(&g_agg1[(size_t)dA1 * 32 + o], accA[t][2], accA[t][3]);
        red_v2(&g_agg1[(size_t)dB0 * 32 + o], accB[t][0], accB[t][1]);
        red_v2(&g_agg1[(size_t)dB1 * 32 + o], accB[t][2], accB[t][3]);
    }
}

// ---------------- node1: h1 = relu(x@root1 + agg1 + bias1) -> fp16 pairs ----------------
__global__ void __launch_bounds__(256)
node1_kernel(const float* __restrict__ x,
             const float* __restrict__ root1, const float* __restrict__ bias1)
{
    __shared__ float sR1[16 * 32];
    __shared__ float sB1[32];
    __shared__ float sX[16][17];

    const int tid = threadIdx.x;
    const int nb  = blockIdx.x * 16;

    for (int i = tid; i < 512; i += 256) sR1[i] = root1[i];
    if (tid < 32) sB1[tid] = bias1[tid];
    if (tid < 256) {
        const int nl = tid >> 4, i = tid & 15;
        sX[nl][i] = x[(size_t)(nb + nl) * 16 + i];
    }
    __syncthreads();

    const int nl = tid >> 4;
    const int pr = tid & 15;
    const int n  = nb + nl;
    const int o0 = 2 * pr, o1 = o0 + 1;

    float a0 = sB1[o0] + g_agg1[(size_t)n * 32 + o0];
    float a1 = sB1[o1] + g_agg1[(size_t)n * 32 + o1];
    #pragma unroll
    for (int i = 0; i < 16; i++) {
        const float xi = sX[nl][i];
        a0 += xi * sR1[i * 32 + o0];
        a1 += xi * sR1[i * 32 + o1];
    }
    g_h1h2[(size_t)n * 16 + pr] = pack_half2(fmaxf(a0, 0.f), fmaxf(a1, 0.f));
}

// ---------------- edge2_z: warp per 32-edge tile (dynamic smem, 55.9 KB) ----------------
__global__ void __launch_bounds__(256)
edge2_z_kernel(const float* __restrict__ ea,
               const int*   __restrict__ ei,
               const float* __restrict__ w1, const float* __restrict__ b1)
{
    extern __shared__ __align__(16) char smem[];
    unsigned* sBt  = (unsigned*)(smem + E2_OFF_BT);   // [B2TAB_N]
    float*    sW1  = (float*)   (smem + E2_OFF_W1);   // [128]
    float*    sB1v = (float*)   (smem + E2_OFF_B1);   // [16]
    unsigned* sHH  = (unsigned*)(smem + E2_OFF_HH);   // [8][32][20]
    unsigned* sH2  = (unsigned*)(smem + E2_OFF_H2);   // [8][32][17]

    const int tid  = threadIdx.x;
    const int lane = tid & 31;
    const int wid  = tid >> 5;

    for (int i = tid; i < B2TAB_N; i += 256) sBt[i] = g_B2tab[i];
    if (tid < F_EDGE * HID) sW1[tid] = w1[tid];
    if (tid < HID) sB1v[tid] = b1[tid];
    __syncthreads();

    const int wtile = blockIdx.x * 8 + wid;
    if (wtile >= WTILES1) return;
    const int e0 = wtile * 32;

    unsigned* wHH = sHH + wid * 32 * 20;
    unsigned* wH2 = sH2 + wid * 32 * 17;

    const int src_reg = ei[e0 + lane];
    const int dst_reg = ei[N_EDGES + e0 + lane];

    // h1 gather: 2 lanes per edge, 32B each, 2 iterations
    #pragma unroll
    for (int it = 0; it < 2; it++) {
        const int e = it * 16 + (lane >> 1), part = lane & 1;
        const int s = __shfl_sync(0xffffffffu, src_reg, e);
        const uint4 va = *(const uint4*)(g_h1h2 + (size_t)s * 16 + part * 8);
        const uint4 vb = *(const uint4*)(g_h1h2 + (size_t)s * 16 + part * 8 + 4);
        *(uint4*)&wHH[e * 20 + part * 8]     = va;
        *(uint4*)&wHH[e * 20 + part * 8 + 4] = vb;
    }
    // hid: each lane = one edge
    {
        const float4 v0 = *(const float4*)(ea + (size_t)(e0 + lane) * 8);
        const float4 v1 = *(const float4*)(ea + (size_t)(e0 + lane) * 8 + 4);
        const float eav[8] = {v0.x, v0.y, v0.z, v0.w, v1.x, v1.y, v1.z, v1.w};
        #pragma unroll
        for (int h = 0; h < HID; h++) {
            float s = sB1v[h];
            #pragma unroll
            for (int j = 0; j < F_EDGE; j++) s += eav[j] * sW1[j * HID + h];
            const float v = fmaxf(s, 0.f);
            wH2[lane * 17 + h] = pack_half2(v, v);
        }
    }
    __syncwarp();

    const int row0 = lane >> 2, row1 = row0 + 8;
    const int ra0 = row0, ra1 = row1;
    const int rb0 = row0 + 16, rb1 = row1 + 16;
    const int k0 = (lane & 3) * 2;
    const int p  = k0 >> 1;

    const unsigned xa[4] = {wHH[ra0*20 + p], wHH[ra0*20 + p + 4],
                            wHH[ra0*20 + p + 8], wHH[ra0*20 + p + 12]};
    const unsigned ya[4] = {wHH[ra1*20 + p], wHH[ra1*20 + p + 4],
                            wHH[ra1*20 + p + 8], wHH[ra1*20 + p + 12]};
    const unsigned xb[4] = {wHH[rb0*20 + p], wHH[rb0*20 + p + 4],
                            wHH[rb0*20 + p + 8], wHH[rb0*20 + p + 12]};
    const unsigned yb[4] = {wHH[rb1*20 + p], wHH[rb1*20 + p + 4],
                            wHH[rb1*20 + p + 8], wHH[rb1*20 + p + 12]};

    float accA[2][4] = {}, accB[2][4] = {};
    #pragma unroll
    for (int m = 0; m < 16; m++) {
        const unsigned ha0 = wH2[ra0*17 + m], ha1 = wH2[ra1*17 + m];
        const unsigned hb0 = wH2[rb0*17 + m], hb1 = wH2[rb1*17 + m];
        #pragma unroll
        for (int half = 0; half < 2; half++) {   // ks = 2m + half
            const unsigned aA[4] = {hmul2u(ha0, xa[2*half]), hmul2u(ha1, ya[2*half]),
                                    hmul2u(ha0, xa[2*half+1]), hmul2u(ha1, ya[2*half+1])};
            const unsigned aB[4] = {hmul2u(hb0, xb[2*half]), hmul2u(hb1, yb[2*half]),
                                    hmul2u(hb0, xb[2*half+1]), hmul2u(hb1, yb[2*half+1])};
            #pragma unroll
            for (int t = 0; t < 2; t++) {
                const uint2 bv = *(const uint2*)&sBt[((t * B2_KS + 2*m + half) * 32 + lane) * 2];
                const unsigned b[2] = {bv.x, bv.y};
                mma16816(accA[t], aA, b);
                mma16816(accB[t], aB, b);
            }
        }
    }
    #pragma unroll
    for (int half = 0; half < 2; half++) {   // bias ks = 32 + half (z = h1 halves)
        const unsigned aA[4] = {xa[2*half], ya[2*half], xa[2*half+1], ya[2*half+1]};
        const unsigned aB[4] = {xb[2*half], yb[2*half], xb[2*half+1], yb[2*half+1]};
        #pragma unroll
        for (int t = 0; t < 2; t++) {
            const uint2 bv = *(const uint2*)&sBt[((t * B2_KS + 32 + half) * 32 + lane) * 2];
            const unsigned b[2] = {bv.x, bv.y};
            mma16816(accA[t], aA, b);
            mma16816(accB[t], aB, b);
        }
    }

    const int dA0 = __shfl_sync(0xffffffffu, dst_reg, ra0);
    const int dA1 = __shfl_sync(0xffffffffu, dst_reg, ra1);
    const int dB0 = __shfl_sync(0xffffffffu, dst_reg, rb0);
    const int dB1 = __shfl_sync(0xffffffffu, dst_reg, rb1);
    #pragma unroll
    for (int t = 0; t < 2; t++) {
        const int o = t * 8 + k0;
        red_v2(&g_agg2[(size_t)dA0 * 16 + o], accA[t][0], accA[t][1]);
        red_v2(&g_agg2[(size_t)dA1 * 16 + o], accA[t][2], accA[t][3]);
        red_v2(&g_agg2[(size_t)dB0 * 16 + o], accB[t][0], accB[t][1]);
        red_v2(&g_agg2[(size_t)dB1 * 16 + o], accB[t][2], accB[t][3]);
    }
}

// ---------------- fused node2 + pool (h1 from fp16 pairs) ----------------
__global__ void __launch_bounds__(256)
node2_pool_kernel(const int* __restrict__ batch,
                  const float* __restrict__ root2, const float* __restrict__ bias2)
{
    __shared__ float sR2[32 * 16];
    __shared__ float sB2v[16];
    for (int idx = threadIdx.x; idx < 512; idx += 256) sR2[idx] = root2[idx];
    if (threadIdx.x < 16) sB2v[threadIdx.x] = bias2[threadIdx.x];
    __syncthreads();

    const int w = (blockIdx.x * 256 + threadIdx.x) >> 5;
    const int lane = threadIdx.x & 31;
    const int half = lane >> 4;
    const int o = lane & 15;
    const int n = 2 * w + half;
    if (n >= N_NODES) return;

    const unsigned hp = g_h1h2[(size_t)n * 16 + o];   // pair (2o, 2o+1)

    float acc = sB2v[o] + g_agg2[(size_t)n * 16 + o];
    #pragma unroll
    for (int i = 0; i < 16; i++) {
        const unsigned pi = __shfl_sync(0xffffffffu, hp, i, 16);
        const float2 f = __half22float2(*reinterpret_cast<const __half2*>(&pi));
        acc += f.x * sR2[(2 * i) * 16 + o] + f.y * sR2[(2 * i + 1) * 16 + o];
    }

    const float v = fmaxf(acc, 0.f);
    const int g = batch[n];
    atomicAdd(&g_pool[g * 16 + o], v);
    if (o == 0) atomicAdd(&g_cnt[g], 1.0f);
}

// ---------------- readout MLP ----------------
__global__ void readout_kernel(const float* __restrict__ l1w, const float* __restrict__ l1b,
                               const float* __restrict__ l2w, const float* __restrict__ l2b,
                               float* __restrict__ out)
{
    const int g = blockIdx.x * blockDim.x + threadIdx.x;
    if (g >= N_GRAPHS) return;
    const float inv = 1.0f / fmaxf(g_cnt[g], 1.0f);
    float p[16];
    #pragma unroll
    for (int o = 0; o < 16; o++) p[o] = g_pool[g * 16 + o] * inv;
    float acc = l2b[0];
    #pragma unroll
    for (int j = 0; j < 8; j++) {
        float s = l1b[j];
        #pragma unroll
        for (int o = 0; o < 16; o++) s += p[o] * l1w[o * 8 + j];
        acc += fmaxf(s, 0.f) * l2w[j];
    }
    out[g] = acc;
}

// ---------------- launch ----------------
extern "C" void kernel_launch(void* const* d_in, const int* in_sizes, int n_in,
                              void* d_out, int out_size)
{
    const float* x      = (const float*)d_in[0];
    const float* ea     = (const float*)d_in[1];
    const int*   ei     = (const int*)  d_in[2];
    const int*   batch  = (const int*)  d_in[3];
    const float* nn1_w1 = (const float*)d_in[4];
    const float* nn1_b1 = (const float*)d_in[5];
    const float* nn1_w2 = (const float*)d_in[6];
    const float* nn1_b2 = (const float*)d_in[7];
    const float* root1  = (const float*)d_in[8];
    const float* bias1  = (const float*)d_in[9];
    const float* nn2_w1 = (const float*)d_in[10];
    const float* nn2_b1 = (const float*)d_in[11];
    const float* nn2_w2 = (const float*)d_in[12];
    const float* nn2_b2 = (const float*)d_in[13];
    const float* root2  = (const float*)d_in[14];
    const float* bias2  = (const float*)d_in[15];
    const float* lin1_w = (const float*)d_in[16];
    const float* lin1_b = (const float*)d_in[17];
    const float* lin2_w = (const float*)d_in[18];
    const float* lin2_b = (const float*)d_in[19];
    float* out = (float*)d_out;

    // opt-in >48KB dynamic smem for edge2 (host-side attr; graph-capture safe)
    static int attr_done = 0;
    if (!attr_done) {
        cudaFuncSetAttribute(edge2_z_kernel,
                             cudaFuncAttributeMaxDynamicSharedMemorySize, E2_SMEM);
        attr_done = 1;
    }

    zero_all_kernel<<<(N_NODES * 32 + 255) / 256, 256>>>();
    prep_tabs_kernel<<<(B1TAB_N + 255) / 256, 256>>>(nn1_w2, nn1_b2, nn2_w2, nn2_b2);
    prep_xh2_kernel<<<(N_NODES * 8 + 255) / 256, 256>>>(x);

    const int egrid = (WTILES1 + 7) / 8;   // 1563 blocks of 8 warp-tiles

    // layer 1
    edge1_z_kernel<<<egrid, 256>>>(ea, ei, nn1_w1, nn1_b1);

    // node update 1 -> fp16 h1
    node1_kernel<<<N_NODES / 16, 256>>>(x, root1, bias1);

    // layer 2
    edge2_z_kernel<<<egrid, 256, E2_SMEM>>>(ea, ei, nn2_w1, nn2_b1);

    // node update 2 + pooling
    node2_pool_kernel<<<(N_NODES / 2 * 32 + 255) / 256, 256>>>(batch, root2, bias2);

    // readout
    readout_kernel<<<(N_GRAPHS + 255) / 256, 256>>>(lin1_w, lin1_b, lin2_w, lin2_b, out);
}

// round 11
// speedup vs baseline: 5.6143x; 1.0286x over previous
#include <cuda_runtime.h>
#include <cuda_fp16.h>

#define N_NODES  100000
#define N_EDGES  400000
#define N_GRAPHS 2000
#define F_EDGE   8
#define HID      16

// z-GEMM B-fragment tables, quad-packed per t-pair for LDS.128:
//   idx = (((tp*KS + ks)*32 + lane)*4 + tt*2 + r,  t = 2*tp + tt
// Layer1: msg[E x 32] = Z1[E x 272] @ B1[272 x 32];  z1[c]=hid[c>>4]*x[c&15] (c<256), =x[c-256]
// Layer2: msg[E x 16] = Z2[E x 544] @ B2[544 x 16];  z2[c]=hid[c>>5]*h1[c&31] (c<512), =h1[c-512]
#define B1_TILES 4
#define B1_KS    17
#define B2_TILES 2
#define B2_KS    34
#define B1TAB_N (B1_TILES * B1_KS * 2 * 32)   // 4352
#define B2TAB_N (B2_TILES * B2_KS * 2 * 32)   // 4352

#define WTILES1 (N_EDGES / 32)                // 12500 warp-tiles of 32 edges

// edge2 dynamic smem layout (bytes)
#define E2_OFF_BT   0
#define E2_OFF_W1   (E2_OFF_BT + B2TAB_N * 4)            // 17408
#define E2_OFF_B1   (E2_OFF_W1 + F_EDGE * HID * 4)       // 17920
#define E2_OFF_HH   (E2_OFF_B1 + 64)                     // 17984 (16B aligned)
#define E2_OFF_H2   (E2_OFF_HH + 8 * 32 * 20 * 4)        // 38464
#define E2_SMEM     (E2_OFF_H2 + 8 * 32 * 17 * 4)        // 55872

// ---------------- scratch ----------------
__device__ float    g_agg1[N_NODES * 32];
__device__ float    g_agg2[N_NODES * 16];
__device__ float    g_pool[N_GRAPHS * 16];
__device__ float    g_cnt [N_GRAPHS];
__device__ unsigned g_xh2 [N_NODES * 8];    // x rows as 8 packed half2
__device__ unsigned g_h1h2[N_NODES * 16];   // h1 rows as 16 packed half2
__device__ unsigned g_B1tab[B1TAB_N];
__device__ unsigned g_B2tab[B2TAB_N];

__global__ void zero_all_kernel() {
    int i = blockIdx.x * blockDim.x + threadIdx.x;
    if (i < N_NODES * 32) g_agg1[i] = 0.f;
    if (i < N_NODES * 16) g_agg2[i] = 0.f;
    if (i < N_GRAPHS * 16) g_pool[i] = 0.f;
    if (i < N_GRAPHS) g_cnt[i] = 0.f;
}

// ---------------- helpers ----------------
__device__ __forceinline__ unsigned pack_half2(float a, float b) {
    __half2 h = __floats2half2_rn(a, b);
    return *reinterpret_cast<unsigned*>(&h);
}
__device__ __forceinline__ unsigned hmul2u(unsigned a, unsigned b) {
    __half2 r = __hmul2(*reinterpret_cast<__half2*>(&a), *reinterpret_cast<__half2*>(&b));
    return *reinterpret_cast<unsigned*>(&r);
}
__device__ __forceinline__ void mma16816(float c[4], const unsigned a[4], unsigned b0, unsigned b1) {
    asm volatile("mma.sync.aligned.m16n8k16.row.col.f32.f16.f16.f32 "
                 "{%0,%1,%2,%3}, {%4,%5,%6,%7}, {%8,%9}, {%0,%1,%2,%3};\n"
                 : "+f"(c[0]), "+f"(c[1]), "+f"(c[2]), "+f"(c[3])
                 : "r"(a[0]), "r"(a[1]), "r"(a[2]), "r"(a[3]),
                   "r"(b0), "r"(b1));
}
__device__ __forceinline__ void red_v2(float* p, float a, float b) {
    asm volatile("red.global.add.v2.f32 [%0], {%1, %2};" :: "l"(p), "f"(a), "f"(b) : "memory");
}

// ---------------- prep: B tables + x fp16 conversion ----------------
// Fragment convention (R6-verified): (tile t, k-step ks), reg r holds
//   B[16ks + (lane&3)*2 + 8r + {0,1}, col = t*8 + (lane>>2)]
__global__ void __launch_bounds__(256)
prep_tabs_kernel(const float* __restrict__ w2_1, const float* __restrict__ b2_1,
                 const float* __restrict__ w2_2, const float* __restrict__ b2_2)
{
    const int idx = blockIdx.x * 256 + threadIdx.x;
    if (idx < B1TAB_N) {
        const int r    = idx & 1;
        const int tt   = (idx >> 1) & 1;
        const int lane = (idx >> 2) & 31;
        const int ks   = (idx >> 7) % B1_KS;
        const int tp   = idx / (B1_KS * 128);
        const int t    = tp * 2 + tt;
        const int o    = t * 8 + (lane >> 2);
        const int c    = 16 * ks + (lane & 3) * 2 + r * 8;  // even
        float v0, v1;
        if (c < 256) { const int h = c >> 4, i = c & 15;
            v0 = w2_1[h * 512 + i * 32 + o]; v1 = w2_1[h * 512 + (i + 1) * 32 + o];
        } else { const int i = c - 256;
            v0 = b2_1[i * 32 + o]; v1 = b2_1[(i + 1) * 32 + o];
        }
        g_B1tab[idx] = pack_half2(v0, v1);
    }
    if (idx < B2TAB_N) {
        const int r    = idx & 1;
        const int tt   = (idx >> 1) & 1;
        const int lane = (idx >> 2) & 31;
        const int ks   = (idx >> 7) % B2_KS;
        const int t    = tt;   // single t-pair
        const int o    = t * 8 + (lane >> 2);
        const int c    = 16 * ks + (lane & 3) * 2 + r * 8;  // even
        float v0, v1;
        if (c < 512) { const int h = c >> 5, i = c & 31;
            v0 = w2_2[h * 512 + i * 16 + o]; v1 = w2_2[h * 512 + (i + 1) * 16 + o];
        } else { const int i = c - 512;
            v0 = b2_2[i * 16 + o]; v1 = b2_2[(i + 1) * 16 + o];
        }
        g_B2tab[idx] = pack_half2(v0, v1);
    }
}

__global__ void __launch_bounds__(256)
prep_xh2_kernel(const float* __restrict__ x)
{
    const int p = blockIdx.x * 256 + threadIdx.x;
    if (p < N_NODES * 8)
        g_xh2[p] = pack_half2(x[2 * p], x[2 * p + 1]);
}

// ---------------- edge1_z: warp per 32-edge tile (2 m-tiles share B regs) ----------------
__global__ void __launch_bounds__(256, 4)
edge1_z_kernel(const float* __restrict__ ea,
               const int*   __restrict__ ei,
               const float* __restrict__ w1, const float* __restrict__ b1)
{
    __shared__ __align__(16) unsigned sBt[B1TAB_N];   // 17 KB
    __shared__ float    sW1[F_EDGE * HID];
    __shared__ float    sB1v[HID];
    __shared__ __align__(16) unsigned sXH[8][32][12]; // x pairs (8/edge) 12 KB
    __shared__ unsigned sH2[8][32][17];               // hid dup-pairs   17 KB

    const int tid  = threadIdx.x;
    const int lane = tid & 31;
    const int wid  = tid >> 5;

    for (int i = tid; i < B1TAB_N; i += 256) sBt[i] = g_B1tab[i];
    if (tid < F_EDGE * HID) sW1[tid] = w1[tid];
    if (tid < HID) sB1v[tid] = b1[tid];
    __syncthreads();

    const int wtile = blockIdx.x * 8 + wid;
    if (wtile >= WTILES1) return;
    const int e0 = wtile * 32;

    const int src_reg = ei[e0 + lane];
    const int dst_reg = ei[N_EDGES + e0 + lane];

    // x gather: 2 lanes per edge, 2 iterations
    #pragma unroll
    for (int it = 0; it < 2; it++) {
        const int e = it * 16 + (lane >> 1), part = lane & 1;
        const int s = __shfl_sync(0xffffffffu, src_reg, e);
        const uint4 v = *(const uint4*)(g_xh2 + (size_t)s * 8 + part * 4);
        *(uint4*)&sXH[wid][e][part * 4] = v;
    }
    // hid: each lane = one edge, all 16 h
    {
        const float4 v0 = *(const float4*)(ea + (size_t)(e0 + lane) * 8);
        const float4 v1 = *(const float4*)(ea + (size_t)(e0 + lane) * 8 + 4);
        const float eav[8] = {v0.x, v0.y, v0.z, v0.w, v1.x, v1.y, v1.z, v1.w};
        #pragma unroll
        for (int h = 0; h < HID; h++) {
            float s = sB1v[h];
            #pragma unroll
            for (int j = 0; j < F_EDGE; j++) s += eav[j] * sW1[j * HID + h];
            const float v = fmaxf(s, 0.f);
            sH2[wid][lane][h] = pack_half2(v, v);
        }
    }
    __syncwarp();

    const int row0 = lane >> 2, row1 = row0 + 8;
    const int ra0 = row0, ra1 = row1;           // m-tile 0 edges
    const int rb0 = row0 + 16, rb1 = row1 + 16; // m-tile 1 edges
    const int k0 = (lane & 3) * 2;
    const int p  = k0 >> 1;

    const unsigned xa0 = sXH[wid][ra0][p], xa1 = sXH[wid][ra0][p + 4];
    const unsigned xa2 = sXH[wid][ra1][p], xa3 = sXH[wid][ra1][p + 4];
    const unsigned xb0 = sXH[wid][rb0][p], xb1 = sXH[wid][rb0][p + 4];
    const unsigned xb2 = sXH[wid][rb1][p], xb3 = sXH[wid][rb1][p + 4];

    float accA[4][4] = {}, accB[4][4] = {};
    #pragma unroll
    for (int ks = 0; ks < 16; ks++) {
        const unsigned ha0 = sH2[wid][ra0][ks], ha1 = sH2[wid][ra1][ks];
        const unsigned hb0 = sH2[wid][rb0][ks], hb1 = sH2[wid][rb1][ks];
        const unsigned aA[4] = {hmul2u(ha0, xa0), hmul2u(ha1, xa2),
                                hmul2u(ha0, xa1), hmul2u(ha1, xa3)};
        const unsigned aB[4] = {hmul2u(hb0, xb0), hmul2u(hb1, xb2),
                                hmul2u(hb0, xb1), hmul2u(hb1, xb3)};
        #pragma unroll
        for (int tp = 0; tp < 2; tp++) {
            const uint4 bv = *(const uint4*)&sBt[((tp * B1_KS + ks) * 32 + lane) * 4];
            mma16816(accA[2*tp],     aA, bv.x, bv.y);
            mma16816(accA[2*tp + 1], aA, bv.z, bv.w);
            mma16816(accB[2*tp],     aB, bv.x, bv.y);
            mma16816(accB[2*tp + 1], aB, bv.z, bv.w);
        }
    }
    {   // bias k-step (z = x)
        const unsigned aA[4] = {xa0, xa2, xa1, xa3};
        const unsigned aB[4] = {xb0, xb2, xb1, xb3};
        #pragma unroll
        for (int tp = 0; tp < 2; tp++) {
            const uint4 bv = *(const uint4*)&sBt[((tp * B1_KS + 16) * 32 + lane) * 4];
            mma16816(accA[2*tp],     aA, bv.x, bv.y);
            mma16816(accA[2*tp + 1], aA, bv.z, bv.w);
            mma16816(accB[2*tp],     aB, bv.x, bv.y);
            mma16816(accB[2*tp + 1], aB, bv.z, bv.w);
        }
    }

    const int dA0 = __shfl_sync(0xffffffffu, dst_reg, ra0);
    const int dA1 = __shfl_sync(0xffffffffu, dst_reg, ra1);
    const int dB0 = __shfl_sync(0xffffffffu, dst_reg, rb0);
    const int dB1 = __shfl_sync(0xffffffffu, dst_reg, rb1);
    #pragma unroll
    for (int t = 0; t < 4; t++) {
        const int o = t * 8 + k0;
        red_v2(&g_agg1[(size_t)dA0 * 32 + o], accA[t][0], accA[t][1]);
        red_v2(&g_agg1[(size_t)dA1 * 32 + o], accA[t][2], accA[t][3]);
        red_v2(&g_agg1[(size_t)dB0 * 32 + o], accB[t][0], accB[t][1]);
        red_v2(&g_agg1[(size_t)dB1 * 32 + o], accB[t][2], accB[t][3]);
    }
}

// ---------------- node1: h1 = relu(x@root1 + agg1 + bias1) -> fp16 pairs ----------------
__global__ void __launch_bounds__(256)
node1_kernel(const float* __restrict__ x,
             const float* __restrict__ root1, const float* __restrict__ bias1)
{
    __shared__ float sR1[16 * 32];
    __shared__ float sB1[32];
    __shared__ float sX[16][17];

    const int tid = threadIdx.x;
    const int nb  = blockIdx.x * 16;

    for (int i = tid; i < 512; i += 256) sR1[i] = root1[i];
    if (tid < 32) sB1[tid] = bias1[tid];
    if (tid < 256) {
        const int nl = tid >> 4, i = tid & 15;
        sX[nl][i] = x[(size_t)(nb + nl) * 16 + i];
    }
    __syncthreads();

    const int nl = tid >> 4;
    const int pr = tid & 15;
    const int n  = nb + nl;
    const int o0 = 2 * pr, o1 = o0 + 1;

    float a0 = sB1[o0] + g_agg1[(size_t)n * 32 + o0];
    float a1 = sB1[o1] + g_agg1[(size_t)n * 32 + o1];
    #pragma unroll
    for (int i = 0; i < 16; i++) {
        const float xi = sX[nl][i];
        a0 += xi * sR1[i * 32 + o0];
        a1 += xi * sR1[i * 32 + o1];
    }
    g_h1h2[(size_t)n * 16 + pr] = pack_half2(fmaxf(a0, 0.f), fmaxf(a1, 0.f));
}

// ---------------- edge2_z: warp per 32-edge tile (dynamic smem, 55.9 KB) ----------------
__global__ void __launch_bounds__(256, 4)
edge2_z_kernel(const float* __restrict__ ea,
               const int*   __restrict__ ei,
               const float* __restrict__ w1, const float* __restrict__ b1)
{
    extern __shared__ __align__(16) char smem[];
    unsigned* sBt  = (unsigned*)(smem + E2_OFF_BT);   // [B2TAB_N]
    float*    sW1  = (float*)   (smem + E2_OFF_W1);   // [128]
    float*    sB1v = (float*)   (smem + E2_OFF_B1);   // [16]
    unsigned* sHH  = (unsigned*)(smem + E2_OFF_HH);   // [8][32][20]
    unsigned* sH2  = (unsigned*)(smem + E2_OFF_H2);   // [8][32][17]

    const int tid  = threadIdx.x;
    const int lane = tid & 31;
    const int wid  = tid >> 5;

    for (int i = tid; i < B2TAB_N; i += 256) sBt[i] = g_B2tab[i];
    if (tid < F_EDGE * HID) sW1[tid] = w1[tid];
    if (tid < HID) sB1v[tid] = b1[tid];
    __syncthreads();

    const int wtile = blockIdx.x * 8 + wid;
    if (wtile >= WTILES1) return;
    const int e0 = wtile * 32;

    unsigned* wHH = sHH + wid * 32 * 20;
    unsigned* wH2 = sH2 + wid * 32 * 17;

    const int src_reg = ei[e0 + lane];
    const int dst_reg = ei[N_EDGES + e0 + lane];

    // h1 gather: 2 lanes per edge, 32B each, 2 iterations
    #pragma unroll
    for (int it = 0; it < 2; it++) {
        const int e = it * 16 + (lane >> 1), part = lane & 1;
        const int s = __shfl_sync(0xffffffffu, src_reg, e);
        const uint4 va = *(const uint4*)(g_h1h2 + (size_t)s * 16 + part * 8);
        const uint4 vb = *(const uint4*)(g_h1h2 + (size_t)s * 16 + part * 8 + 4);
        *(uint4*)&wHH[e * 20 + part * 8]     = va;
        *(uint4*)&wHH[e * 20 + part * 8 + 4] = vb;
    }
    // hid: each lane = one edge
    {
        const float4 v0 = *(const float4*)(ea + (size_t)(e0 + lane) * 8);
        const float4 v1 = *(const float4*)(ea + (size_t)(e0 + lane) * 8 + 4);
        const float eav[8] = {v0.x, v0.y, v0.z, v0.w, v1.x, v1.y, v1.z, v1.w};
        #pragma unroll
        for (int h = 0; h < HID; h++) {
            float s = sB1v[h];
            #pragma unroll
            for (int j = 0; j < F_EDGE; j++) s += eav[j] * sW1[j * HID + h];
            const float v = fmaxf(s, 0.f);
            wH2[lane * 17 + h] = pack_half2(v, v);
        }
    }
    __syncwarp();

    const int row0 = lane >> 2, row1 = row0 + 8;
    const int ra0 = row0, ra1 = row1;
    const int rb0 = row0 + 16, rb1 = row1 + 16;
    const int k0 = (lane & 3) * 2;
    const int p  = k0 >> 1;

    const unsigned xa[4] = {wHH[ra0*20 + p], wHH[ra0*20 + p + 4],
                            wHH[ra0*20 + p + 8], wHH[ra0*20 + p + 12]};
    const unsigned ya[4] = {wHH[ra1*20 + p], wHH[ra1*20 + p + 4],
                            wHH[ra1*20 + p + 8], wHH[ra1*20 + p + 12]};
    const unsigned xb[4] = {wHH[rb0*20 + p], wHH[rb0*20 + p + 4],
                            wHH[rb0*20 + p + 8], wHH[rb0*20 + p + 12]};
    const unsigned yb[4] = {wHH[rb1*20 + p], wHH[rb1*20 + p + 4],
                            wHH[rb1*20 + p + 8], wHH[rb1*20 + p + 12]};

    float accA[2][4] = {}, accB[2][4] = {};
    #pragma unroll
    for (int m = 0; m < 16; m++) {
        const unsigned ha0 = wH2[ra0*17 + m], ha1 = wH2[ra1*17 + m];
        const unsigned hb0 = wH2[rb0*17 + m], hb1 = wH2[rb1*17 + m];
        #pragma unroll
        for (int half = 0; half < 2; half++) {   // ks = 2m + half
            const unsigned aA[4] = {hmul2u(ha0, xa[2*half]), hmul2u(ha1, ya[2*half]),
                                    hmul2u(ha0, xa[2*half+1]), hmul2u(ha1, ya[2*half+1])};
            const unsigned aB[4] = {hmul2u(hb0, xb[2*half]), hmul2u(hb1, yb[2*half]),
                                    hmul2u(hb0, xb[2*half+1]), hmul2u(hb1, yb[2*half+1])};
            const uint4 bv = *(const uint4*)&sBt[((2*m + half) * 32 + lane) * 4];
            mma16816(accA[0], aA, bv.x, bv.y);
            mma16816(accA[1], aA, bv.z, bv.w);
            mma16816(accB[0], aB, bv.x, bv.y);
            mma16816(accB[1], aB, bv.z, bv.w);
        }
    }
    #pragma unroll
    for (int half = 0; half < 2; half++) {   // bias ks = 32 + half (z = h1 halves)
        const unsigned aA[4] = {xa[2*half], ya[2*half], xa[2*half+1], ya[2*half+1]};
        const unsigned aB[4] = {xb[2*half], yb[2*half], xb[2*half+1], yb[2*half+1]};
        const uint4 bv = *(const uint4*)&sBt[((32 + half) * 32 + lane) * 4];
        mma16816(accA[0], aA, bv.x, bv.y);
        mma16816(accA[1], aA, bv.z, bv.w);
        mma16816(accB[0], aB, bv.x, bv.y);
        mma16816(accB[1], aB, bv.z, bv.w);
    }

    const int dA0 = __shfl_sync(0xffffffffu, dst_reg, ra0);
    const int dA1 = __shfl_sync(0xffffffffu, dst_reg, ra1);
    const int dB0 = __shfl_sync(0xffffffffu, dst_reg, rb0);
    const int dB1 = __shfl_sync(0xffffffffu, dst_reg, rb1);
    #pragma unroll
    for (int t = 0; t < 2; t++) {
        const int o = t * 8 + k0;
        red_v2(&g_agg2[(size_t)dA0 * 16 + o], accA[t][0], accA[t][1]);
        red_v2(&g_agg2[(size_t)dA1 * 16 + o], accA[t][2], accA[t][3]);
        red_v2(&g_agg2[(size_t)dB0 * 16 + o], accB[t][0], accB[t][1]);
        red_v2(&g_agg2[(size_t)dB1 * 16 + o], accB[t][2], accB[t][3]);
    }
}

// ---------------- fused node2 + pool (h1 from fp16 pairs) ----------------
__global__ void __launch_bounds__(256)
node2_pool_kernel(const int* __restrict__ batch,
                  const float* __restrict__ root2, const float* __restrict__ bias2)
{
    __shared__ float sR2[32 * 16];
    __shared__ float sB2v[16];
    for (int idx = threadIdx.x; idx < 512; idx += 256) sR2[idx] = root2[idx];
    if (threadIdx.x < 16) sB2v[threadIdx.x] = bias2[threadIdx.x];
    __syncthreads();

    const int w = (blockIdx.x * 256 + threadIdx.x) >> 5;
    const int lane = threadIdx.x & 31;
    const int half = lane >> 4;
    const int o = lane & 15;
    const int n = 2 * w + half;
    if (n >= N_NODES) return;

    const unsigned hp = g_h1h2[(size_t)n * 16 + o];   // pair (2o, 2o+1)

    float acc = sB2v[o] + g_agg2[(size_t)n * 16 + o];
    #pragma unroll
    for (int i = 0; i < 16; i++) {
        const unsigned pi = __shfl_sync(0xffffffffu, hp, i, 16);
        const float2 f = __half22float2(*reinterpret_cast<const __half2*>(&pi));
        acc += f.x * sR2[(2 * i) * 16 + o] + f.y * sR2[(2 * i + 1) * 16 + o];
    }

    const float v = fmaxf(acc, 0.f);
    const int g = batch[n];
    atomicAdd(&g_pool[g * 16 + o], v);
    if (o == 0) atomicAdd(&g_cnt[g], 1.0f);
}

// ---------------- readout MLP ----------------
__global__ void readout_kernel(const float* __restrict__ l1w, const float* __restrict__ l1b,
                               const float* __restrict__ l2w, const float* __restrict__ l2b,
                               float* __restrict__ out)
{
    const int g = blockIdx.x * blockDim.x + threadIdx.x;
    if (g >= N_GRAPHS) return;
    const float inv = 1.0f / fmaxf(g_cnt[g], 1.0f);
    float p[16];
    #pragma unroll
    for (int o = 0; o < 16; o++) p[o] = g_pool[g * 16 + o] * inv;
    float acc = l2b[0];
    #pragma unroll
    for (int j = 0; j < 8; j++) {
        float s = l1b[j];
        #pragma unroll
        for (int o = 0; o < 16; o++) s += p[o] * l1w[o * 8 + j];
        acc += fmaxf(s, 0.f) * l2w[j];
    }
    out[g] = acc;
}

// ---------------- launch ----------------
extern "C" void kernel_launch(void* const* d_in, const int* in_sizes, int n_in,
                              void* d_out, int out_size)
{
    const float* x      = (const float*)d_in[0];
    const float* ea     = (const float*)d_in[1];
    const int*   ei     = (const int*)  d_in[2];
    const int*   batch  = (const int*)  d_in[3];
    const float* nn1_w1 = (const float*)d_in[4];
    const float* nn1_b1 = (const float*)d_in[5];
    const float* nn1_w2 = (const float*)d_in[6];
    const float* nn1_b2 = (const float*)d_in[7];
    const float* root1  = (const float*)d_in[8];
    const float* bias1  = (const float*)d_in[9];
    const float* nn2_w1 = (const float*)d_in[10];
    const float* nn2_b1 = (const float*)d_in[11];
    const float* nn2_w2 = (const float*)d_in[12];
    const float* nn2_b2 = (const float*)d_in[13];
    const float* root2  = (const float*)d_in[14];
    const float* bias2  = (const float*)d_in[15];
    const float* lin1_w = (const float*)d_in[16];
    const float* lin1_b = (const float*)d_in[17];
    const float* lin2_w = (const float*)d_in[18];
    const float* lin2_b = (const float*)d_in[19];
    float* out = (float*)d_out;

    // opt-in >48KB dynamic smem for edge2 (host-side attr; graph-capture safe)
    static int attr_done = 0;
    if (!attr_done) {
        cudaFuncSetAttribute(edge2_z_kernel,
                             cudaFuncAttributeMaxDynamicSharedMemorySize, E2_SMEM);
        attr_done = 1;
    }

    zero_all_kernel<<<(N_NODES * 32 + 255) / 256, 256>>>();
    prep_tabs_kernel<<<(B1TAB_N + 255) / 256, 256>>>(nn1_w2, nn1_b2, nn2_w2, nn2_b2);
    prep_xh2_kernel<<<(N_NODES * 8 + 255) / 256, 256>>>(x);

    const int egrid = (WTILES1 + 7) / 8;   // 1563 blocks of 8 warp-tiles

    // layer 1
    edge1_z_kernel<<<egrid, 256>>>(ea, ei, nn1_w1, nn1_b1);

    // node update 1 -> fp16 h1
    node1_kernel<<<N_NODES / 16, 256>>>(x, root1, bias1);

    // layer 2
    edge2_z_kernel<<<egrid, 256, E2_SMEM>>>(ea, ei, nn2_w1, nn2_b1);

    // node update 2 + pooling
    node2_pool_kernel<<<(N_NODES / 2 * 32 + 255) / 256, 256>>>(batch, root2, bias2);

    // readout
    readout_kernel<<<(N_GRAPHS + 255) / 256, 256>>>(lin1_w, lin1_b, lin2_w, lin2_b, out);
}

// round 12
// speedup vs baseline: 6.1236x; 1.0907x over previous
#include <cuda_runtime.h>
#include <cuda_fp16.h>

#define N_NODES  100000
#define N_EDGES  400000
#define N_GRAPHS 2000
#define F_EDGE   8
#define HID      16

// z-GEMM B-fragment tables, quad-packed per t-pair for LDS.128:
//   idx = (((tp*KS + ks)*32 + lane)*4 + tt*2 + r,  t = 2*tp + tt
// Layer1: msg[E x 32] = Z1[E x 272] @ B1[272 x 32];  z1[c]=hid[c>>4]*x[c&15] (c<256), =x[c-256]
// Layer2: msg[E x 16] = Z2[E x 544] @ B2[544 x 16];  z2[c]=hid[c>>5]*h1[c&31] (c<512), =h1[c-512]
#define B1_TILES 4
#define B1_KS    17
#define B2_TILES 2
#define B2_KS    34
#define B1TAB_N (B1_TILES * B1_KS * 2 * 32)   // 4352
#define B2TAB_N (B2_TILES * B2_KS * 2 * 32)   // 4352

#define WTILES1 (N_EDGES / 32)                // 12500 warp-tiles of 32 edges

// ---------------- scratch ----------------
__device__ float    g_agg1[N_NODES * 32];
__device__ float    g_agg2[N_NODES * 16];
__device__ float    g_pool[N_GRAPHS * 16];
__device__ float    g_cnt [N_GRAPHS];
__device__ unsigned g_xh2 [N_NODES * 8];    // x rows as 8 packed half2
__device__ unsigned g_h1h2[N_NODES * 16];   // h1 rows as 16 packed half2
__device__ unsigned g_B1tab[B1TAB_N];
__device__ unsigned g_B2tab[B2TAB_N];

// ---------------- zero scratch (vectorized) ----------------
__global__ void __launch_bounds__(256)
zero_all_kernel() {
    const int i = blockIdx.x * 256 + threadIdx.x;
    const float4 z = {0.f, 0.f, 0.f, 0.f};
    if (i < N_NODES * 8)  ((float4*)g_agg1)[i] = z;
    if (i < N_NODES * 4)  ((float4*)g_agg2)[i] = z;
    if (i < N_GRAPHS * 4) ((float4*)g_pool)[i] = z;
    if (i < N_GRAPHS / 4) ((float4*)g_cnt)[i]  = z;
}

// ---------------- helpers ----------------
__device__ __forceinline__ unsigned pack_half2(float a, float b) {
    __half2 h = __floats2half2_rn(a, b);
    return *reinterpret_cast<unsigned*>(&h);
}
__device__ __forceinline__ unsigned hmul2u(unsigned a, unsigned b) {
    __half2 r = __hmul2(*reinterpret_cast<__half2*>(&a), *reinterpret_cast<__half2*>(&b));
    return *reinterpret_cast<unsigned*>(&r);
}
// duplicate low/high half of a packed half2: (x,x) / (y,y)
__device__ __forceinline__ unsigned dup_lo(unsigned v) {
    __half2 h = __low2half2(*reinterpret_cast<__half2*>(&v));
    return *reinterpret_cast<unsigned*>(&h);
}
__device__ __forceinline__ unsigned dup_hi(unsigned v) {
    __half2 h = __high2half2(*reinterpret_cast<__half2*>(&v));
    return *reinterpret_cast<unsigned*>(&h);
}
__device__ __forceinline__ void mma16816(float c[4], const unsigned a[4], unsigned b0, unsigned b1) {
    asm volatile("mma.sync.aligned.m16n8k16.row.col.f32.f16.f16.f32 "
                 "{%0,%1,%2,%3}, {%4,%5,%6,%7}, {%8,%9}, {%0,%1,%2,%3};\n"
                 : "+f"(c[0]), "+f"(c[1]), "+f"(c[2]), "+f"(c[3])
                 : "r"(a[0]), "r"(a[1]), "r"(a[2]), "r"(a[3]),
                   "r"(b0), "r"(b1));
}
__device__ __forceinline__ void red_v2(float* p, float a, float b) {
    asm volatile("red.global.add.v2.f32 [%0], {%1, %2};" :: "l"(p), "f"(a), "f"(b) : "memory");
}

// ---------------- prep: B tables + x fp16 conversion ----------------
// Fragment convention (R6-verified): (tile t, k-step ks), reg r holds
//   B[16ks + (lane&3)*2 + 8r + {0,1}, col = t*8 + (lane>>2)]
__global__ void __launch_bounds__(256)
prep_tabs_kernel(const float* __restrict__ w2_1, const float* __restrict__ b2_1,
                 const float* __restrict__ w2_2, const float* __restrict__ b2_2)
{
    const int idx = blockIdx.x * 256 + threadIdx.x;
    if (idx < B1TAB_N) {
        const int r    = idx & 1;
        const int tt   = (idx >> 1) & 1;
        const int lane = (idx >> 2) & 31;
        const int ks   = (idx >> 7) % B1_KS;
        const int tp   = idx / (B1_KS * 128);
        const int t    = tp * 2 + tt;
        const int o    = t * 8 + (lane >> 2);
        const int c    = 16 * ks + (lane & 3) * 2 + r * 8;  // even
        float v0, v1;
        if (c < 256) { const int h = c >> 4, i = c & 15;
            v0 = w2_1[h * 512 + i * 32 + o]; v1 = w2_1[h * 512 + (i + 1) * 32 + o];
        } else { const int i = c - 256;
            v0 = b2_1[i * 32 + o]; v1 = b2_1[(i + 1) * 32 + o];
        }
        g_B1tab[idx] = pack_half2(v0, v1);
    }
    if (idx < B2TAB_N) {
        const int r    = idx & 1;
        const int tt   = (idx >> 1) & 1;
        const int lane = (idx >> 2) & 31;
        const int ks   = (idx >> 7) % B2_KS;
        const int t    = tt;   // single t-pair
        const int o    = t * 8 + (lane >> 2);
        const int c    = 16 * ks + (lane & 3) * 2 + r * 8;  // even
        float v0, v1;
        if (c < 512) { const int h = c >> 5, i = c & 31;
            v0 = w2_2[h * 512 + i * 16 + o]; v1 = w2_2[h * 512 + (i + 1) * 16 + o];
        } else { const int i = c - 512;
            v0 = b2_2[i * 16 + o]; v1 = b2_2[(i + 1) * 16 + o];
        }
        g_B2tab[idx] = pack_half2(v0, v1);
    }
}

__global__ void __launch_bounds__(256)
prep_xh2_kernel(const float* __restrict__ x)
{
    const int p = blockIdx.x * 256 + threadIdx.x;
    if (p < N_NODES * 8)
        g_xh2[p] = pack_half2(x[2 * p], x[2 * p + 1]);
}

// ---------------- edge1_z: warp per 32-edge tile (2 m-tiles share B regs) ----------------
__global__ void __launch_bounds__(256, 4)
edge1_z_kernel(const float* __restrict__ ea,
               const int*   __restrict__ ei,
               const float* __restrict__ w1, const float* __restrict__ b1)
{
    __shared__ __align__(16) unsigned sBt[B1TAB_N];   // 17 KB
    __shared__ float    sW1[F_EDGE * HID];
    __shared__ float    sB1v[HID];
    __shared__ __align__(16) unsigned sXH[8][32][12]; // x pairs (8/edge) 12 KB
    __shared__ unsigned sH2[8][32][9];                // h packed pairs   9 KB

    const int tid  = threadIdx.x;
    const int lane = tid & 31;
    const int wid  = tid >> 5;

    for (int i = tid; i < B1TAB_N; i += 256) sBt[i] = g_B1tab[i];
    if (tid < F_EDGE * HID) sW1[tid] = w1[tid];
    if (tid < HID) sB1v[tid] = b1[tid];
    __syncthreads();

    const int wtile = blockIdx.x * 8 + wid;
    if (wtile >= WTILES1) return;
    const int e0 = wtile * 32;

    const int src_reg = ei[e0 + lane];
    const int dst_reg = ei[N_EDGES + e0 + lane];

    // x gather: 2 lanes per edge, 2 iterations
    #pragma unroll
    for (int it = 0; it < 2; it++) {
        const int e = it * 16 + (lane >> 1), part = lane & 1;
        const int s = __shfl_sync(0xffffffffu, src_reg, e);
        const uint4 v = *(const uint4*)(g_xh2 + (size_t)s * 8 + part * 4);
        *(uint4*)&sXH[wid][e][part * 4] = v;
    }
    // hid: each lane = one edge, packed pairs (h2k, h2k+1)
    {
        const float4 v0 = *(const float4*)(ea + (size_t)(e0 + lane) * 8);
        const float4 v1 = *(const float4*)(ea + (size_t)(e0 + lane) * 8 + 4);
        const float eav[8] = {v0.x, v0.y, v0.z, v0.w, v1.x, v1.y, v1.z, v1.w};
        #pragma unroll
        for (int k = 0; k < 8; k++) {
            float s0 = sB1v[2*k], s1 = sB1v[2*k + 1];
            #pragma unroll
            for (int j = 0; j < F_EDGE; j++) {
                s0 += eav[j] * sW1[j * HID + 2*k];
                s1 += eav[j] * sW1[j * HID + 2*k + 1];
            }
            sH2[wid][lane][k] = pack_half2(fmaxf(s0, 0.f), fmaxf(s1, 0.f));
        }
    }
    __syncwarp();

    const int row0 = lane >> 2, row1 = row0 + 8;
    const int ra0 = row0, ra1 = row1;           // m-tile 0 edges
    const int rb0 = row0 + 16, rb1 = row1 + 16; // m-tile 1 edges
    const int k0 = (lane & 3) * 2;
    const int p  = k0 >> 1;

    const unsigned xa0 = sXH[wid][ra0][p], xa1 = sXH[wid][ra0][p + 4];
    const unsigned xa2 = sXH[wid][ra1][p], xa3 = sXH[wid][ra1][p + 4];
    const unsigned xb0 = sXH[wid][rb0][p], xb1 = sXH[wid][rb0][p + 4];
    const unsigned xb2 = sXH[wid][rb1][p], xb3 = sXH[wid][rb1][p + 4];

    float accA[4][4] = {}, accB[4][4] = {};
    #pragma unroll
    for (int k = 0; k < 8; k++) {
        const unsigned pa0 = sH2[wid][ra0][k], pa1 = sH2[wid][ra1][k];
        const unsigned pb0 = sH2[wid][rb0][k], pb1 = sH2[wid][rb1][k];
        #pragma unroll
        for (int hf = 0; hf < 2; hf++) {
            const int ks = 2*k + hf;
            const unsigned ha0 = hf ? dup_hi(pa0) : dup_lo(pa0);
            const unsigned ha1 = hf ? dup_hi(pa1) : dup_lo(pa1);
            const unsigned hb0 = hf ? dup_hi(pb0) : dup_lo(pb0);
            const unsigned hb1 = hf ? dup_hi(pb1) : dup_lo(pb1);
            const unsigned aA[4] = {hmul2u(ha0, xa0), hmul2u(ha1, xa2),
                                    hmul2u(ha0, xa1), hmul2u(ha1, xa3)};
            const unsigned aB[4] = {hmul2u(hb0, xb0), hmul2u(hb1, xb2),
                                    hmul2u(hb0, xb1), hmul2u(hb1, xb3)};
            #pragma unroll
            for (int tp = 0; tp < 2; tp++) {
                const uint4 bv = *(const uint4*)&sBt[((tp * B1_KS + ks) * 32 + lane) * 4];
                mma16816(accA[2*tp],     aA, bv.x, bv.y);
                mma16816(accA[2*tp + 1], aA, bv.z, bv.w);
                mma16816(accB[2*tp],     aB, bv.x, bv.y);
                mma16816(accB[2*tp + 1], aB, bv.z, bv.w);
            }
        }
    }
    {   // bias k-step (z = x)
        const unsigned aA[4] = {xa0, xa2, xa1, xa3};
        const unsigned aB[4] = {xb0, xb2, xb1, xb3};
        #pragma unroll
        for (int tp = 0; tp < 2; tp++) {
            const uint4 bv = *(const uint4*)&sBt[((tp * B1_KS + 16) * 32 + lane) * 4];
            mma16816(accA[2*tp],     aA, bv.x, bv.y);
            mma16816(accA[2*tp + 1], aA, bv.z, bv.w);
            mma16816(accB[2*tp],     aB, bv.x, bv.y);
            mma16816(accB[2*tp + 1], aB, bv.z, bv.w);
        }
    }

    const int dA0 = __shfl_sync(0xffffffffu, dst_reg, ra0);
    const int dA1 = __shfl_sync(0xffffffffu, dst_reg, ra1);
    const int dB0 = __shfl_sync(0xffffffffu, dst_reg, rb0);
    const int dB1 = __shfl_sync(0xffffffffu, dst_reg, rb1);
    #pragma unroll
    for (int t = 0; t < 4; t++) {
        const int o = t * 8 + k0;
        red_v2(&g_agg1[(size_t)dA0 * 32 + o], accA[t][0], accA[t][1]);
        red_v2(&g_agg1[(size_t)dA1 * 32 + o], accA[t][2], accA[t][3]);
        red_v2(&g_agg1[(size_t)dB0 * 32 + o], accB[t][0], accB[t][1]);
        red_v2(&g_agg1[(size_t)dB1 * 32 + o], accB[t][2], accB[t][3]);
    }
}

// ---------------- node1: h1 = relu(x@root1 + agg1 + bias1) -> fp16 pairs ----------------
__global__ void __launch_bounds__(256)
node1_kernel(const float* __restrict__ x,
             const float* __restrict__ root1, const float* __restrict__ bias1)
{
    __shared__ float sR1[16 * 32];
    __shared__ float sB1[32];
    __shared__ float sX[16][17];

    const int tid = threadIdx.x;
    const int nb  = blockIdx.x * 16;

    for (int i = tid; i < 512; i += 256) sR1[i] = root1[i];
    if (tid < 32) sB1[tid] = bias1[tid];
    if (tid < 256) {
        const int nl = tid >> 4, i = tid & 15;
        sX[nl][i] = x[(size_t)(nb + nl) * 16 + i];
    }
    __syncthreads();

    const int nl = tid >> 4;
    const int pr = tid & 15;
    const int n  = nb + nl;
    const int o0 = 2 * pr, o1 = o0 + 1;

    float a0 = sB1[o0] + g_agg1[(size_t)n * 32 + o0];
    float a1 = sB1[o1] + g_agg1[(size_t)n * 32 + o1];
    #pragma unroll
    for (int i = 0; i < 16; i++) {
        const float xi = sX[nl][i];
        a0 += xi * sR1[i * 32 + o0];
        a1 += xi * sR1[i * 32 + o1];
    }
    g_h1h2[(size_t)n * 16 + pr] = pack_half2(fmaxf(a0, 0.f), fmaxf(a1, 0.f));
}

// ---------------- edge2_z: warp per 32-edge tile (static smem, 47.7 KB) ----------------
__global__ void __launch_bounds__(256, 4)
edge2_z_kernel(const float* __restrict__ ea,
               const int*   __restrict__ ei,
               const float* __restrict__ w1, const float* __restrict__ b1)
{
    __shared__ __align__(16) unsigned sBt[B2TAB_N];   // 17 KB
    __shared__ float    sW1[F_EDGE * HID];
    __shared__ float    sB1v[HID];
    __shared__ __align__(16) unsigned sHH[8][32][20]; // h1 pairs (16/edge) 20.5 KB
    __shared__ unsigned sH2[8][32][9];                // h packed pairs     9 KB

    const int tid  = threadIdx.x;
    const int lane = tid & 31;
    const int wid  = tid >> 5;

    for (int i = tid; i < B2TAB_N; i += 256) sBt[i] = g_B2tab[i];
    if (tid < F_EDGE * HID) sW1[tid] = w1[tid];
    if (tid < HID) sB1v[tid] = b1[tid];
    __syncthreads();

    const int wtile = blockIdx.x * 8 + wid;
    if (wtile >= WTILES1) return;
    const int e0 = wtile * 32;

    const int src_reg = ei[e0 + lane];
    const int dst_reg = ei[N_EDGES + e0 + lane];

    // h1 gather: 2 lanes per edge, 32B each, 2 iterations
    #pragma unroll
    for (int it = 0; it < 2; it++) {
        const int e = it * 16 + (lane >> 1), part = lane & 1;
        const int s = __shfl_sync(0xffffffffu, src_reg, e);
        const uint4 va = *(const uint4*)(g_h1h2 + (size_t)s * 16 + part * 8);
        const uint4 vb = *(const uint4*)(g_h1h2 + (size_t)s * 16 + part * 8 + 4);
        *(uint4*)&sHH[wid][e][part * 8]     = va;
        *(uint4*)&sHH[wid][e][part * 8 + 4] = vb;
    }
    // hid: each lane = one edge, packed pairs
    {
        const float4 v0 = *(const float4*)(ea + (size_t)(e0 + lane) * 8);
        const float4 v1 = *(const float4*)(ea + (size_t)(e0 + lane) * 8 + 4);
        const float eav[8] = {v0.x, v0.y, v0.z, v0.w, v1.x, v1.y, v1.z, v1.w};
        #pragma unroll
        for (int k = 0; k < 8; k++) {
            float s0 = sB1v[2*k], s1 = sB1v[2*k + 1];
            #pragma unroll
            for (int j = 0; j < F_EDGE; j++) {
                s0 += eav[j] * sW1[j * HID + 2*k];
                s1 += eav[j] * sW1[j * HID + 2*k + 1];
            }
            sH2[wid][lane][k] = pack_half2(fmaxf(s0, 0.f), fmaxf(s1, 0.f));
        }
    }
    __syncwarp();

    const int row0 = lane >> 2, row1 = row0 + 8;
    const int ra0 = row0, ra1 = row1;
    const int rb0 = row0 + 16, rb1 = row1 + 16;
    const int k0 = (lane & 3) * 2;
    const int p  = k0 >> 1;

    const unsigned xa[4] = {sHH[wid][ra0][p], sHH[wid][ra0][p + 4],
                            sHH[wid][ra0][p + 8], sHH[wid][ra0][p + 12]};
    const unsigned ya[4] = {sHH[wid][ra1][p], sHH[wid][ra1][p + 4],
                            sHH[wid][ra1][p + 8], sHH[wid][ra1][p + 12]};
    const unsigned xb[4] = {sHH[wid][rb0][p], sHH[wid][rb0][p + 4],
                            sHH[wid][rb0][p + 8], sHH[wid][rb0][p + 12]};
    const unsigned yb[4] = {sHH[wid][rb1][p], sHH[wid][rb1][p + 4],
                            sHH[wid][rb1][p + 8], sHH[wid][rb1][p + 12]};

    float accA[2][4] = {}, accB[2][4] = {};
    #pragma unroll
    for (int j = 0; j < 8; j++) {       // h-pair index: m = 2j+mh
        const unsigned pa0 = sH2[wid][ra0][j], pa1 = sH2[wid][ra1][j];
        const unsigned pb0 = sH2[wid][rb0][j], pb1 = sH2[wid][rb1][j];
        #pragma unroll
        for (int mh = 0; mh < 2; mh++) {
            const int m = 2*j + mh;
            const unsigned ha0 = mh ? dup_hi(pa0) : dup_lo(pa0);
            const unsigned ha1 = mh ? dup_hi(pa1) : dup_lo(pa1);
            const unsigned hb0 = mh ? dup_hi(pb0) : dup_lo(pb0);
            const unsigned hb1 = mh ? dup_hi(pb1) : dup_lo(pb1);
            #pragma unroll
            for (int half = 0; half < 2; half++) {   // ks = 2m + half
                const unsigned aA[4] = {hmul2u(ha0, xa[2*half]), hmul2u(ha1, ya[2*half]),
                                        hmul2u(ha0, xa[2*half+1]), hmul2u(ha1, ya[2*half+1])};
                const unsigned aB[4] = {hmul2u(hb0, xb[2*half]), hmul2u(hb1, yb[2*half]),
                                        hmul2u(hb0, xb[2*half+1]), hmul2u(hb1, yb[2*half+1])};
                const uint4 bv = *(const uint4*)&sBt[((2*m + half) * 32 + lane) * 4];
                mma16816(accA[0], aA, bv.x, bv.y);
                mma16816(accA[1], aA, bv.z, bv.w);
                mma16816(accB[0], aB, bv.x, bv.y);
                mma16816(accB[1], aB, bv.z, bv.w);
            }
        }
    }
    #pragma unroll
    for (int half = 0; half < 2; half++) {   // bias ks = 32 + half (z = h1 halves)
        const unsigned aA[4] = {xa[2*half], ya[2*half], xa[2*half+1], ya[2*half+1]};
        const unsigned aB[4] = {xb[2*half], yb[2*half], xb[2*half+1], yb[2*half+1]};
        const uint4 bv = *(const uint4*)&sBt[((32 + half) * 32 + lane) * 4];
        mma16816(accA[0], aA, bv.x, bv.y);
        mma16816(accA[1], aA, bv.z, bv.w);
        mma16816(accB[0], aB, bv.x, bv.y);
        mma16816(accB[1], aB, bv.z, bv.w);
    }

    const int dA0 = __shfl_sync(0xffffffffu, dst_reg, ra0);
    const int dA1 = __shfl_sync(0xffffffffu, dst_reg, ra1);
    const int dB0 = __shfl_sync(0xffffffffu, dst_reg, rb0);
    const int dB1 = __shfl_sync(0xffffffffu, dst_reg, rb1);
    #pragma unroll
    for (int t = 0; t < 2; t++) {
        const int o = t * 8 + k0;
        red_v2(&g_agg2[(size_t)dA0 * 16 + o], accA[t][0], accA[t][1]);
        red_v2(&g_agg2[(size_t)dA1 * 16 + o], accA[t][2], accA[t][3]);
        red_v2(&g_agg2[(size_t)dB0 * 16 + o], accB[t][0], accB[t][1]);
        red_v2(&g_agg2[(size_t)dB1 * 16 + o], accB[t][2], accB[t][3]);
    }
}

// ---------------- fused node2 + pool (h1 from fp16 pairs) ----------------
__global__ void __launch_bounds__(256)
node2_pool_kernel(const int* __restrict__ batch,
                  const float* __restrict__ root2, const float* __restrict__ bias2)
{
    __shared__ float sR2[32 * 16];
    __shared__ float sB2v[16];
    for (int idx = threadIdx.x; idx < 512; idx += 256) sR2[idx] = root2[idx];
    if (threadIdx.x < 16) sB2v[threadIdx.x] = bias2[threadIdx.x];
    __syncthreads();

    const int w = (blockIdx.x * 256 + threadIdx.x) >> 5;
    const int lane = threadIdx.x & 31;
    const int half = lane >> 4;
    const int o = lane & 15;
    const int n = 2 * w + half;
    if (n >= N_NODES) return;

    const unsigned hp = g_h1h2[(size_t)n * 16 + o];   // pair (2o, 2o+1)

    float acc = sB2v[o] + g_agg2[(size_t)n * 16 + o];
    #pragma unroll
    for (int i = 0; i < 16; i++) {
        const unsigned pi = __shfl_sync(0xffffffffu, hp, i, 16);
        const float2 f = __half22float2(*reinterpret_cast<const __half2*>(&pi));
        acc += f.x * sR2[(2 * i) * 16 + o] + f.y * sR2[(2 * i + 1) * 16 + o];
    }

    const float v = fmaxf(acc, 0.f);
    const int g = batch[n];
    atomicAdd(&g_pool[g * 16 + o], v);
    if (o == 0) atomicAdd(&g_cnt[g], 1.0f);
}

// ---------------- readout MLP ----------------
__global__ void readout_kernel(const float* __restrict__ l1w, const float* __restrict__ l1b,
                               const float* __restrict__ l2w, const float* __restrict__ l2b,
                               float* __restrict__ out)
{
    const int g = blockIdx.x * blockDim.x + threadIdx.x;
    if (g >= N_GRAPHS) return;
    const float inv = 1.0f / fmaxf(g_cnt[g], 1.0f);
    float p[16];
    #pragma unroll
    for (int o = 0; o < 16; o++) p[o] = g_pool[g * 16 + o] * inv;
    float acc = l2b[0];
    #pragma unroll
    for (int j = 0; j < 8; j++) {
        float s = l1b[j];
        #pragma unroll
        for (int o = 0; o < 16; o++) s += p[o] * l1w[o * 8 + j];
        acc += fmaxf(s, 0.f) * l2w[j];
    }
    out[g] = acc;
}

// ---------------- launch ----------------
extern "C" void kernel_launch(void* const* d_in, const int* in_sizes, int n_in,
                              void* d_out, int out_size)
{
    const float* x      = (const float*)d_in[0];
    const float* ea     = (const float*)d_in[1];
    const int*   ei     = (const int*)  d_in[2];
    const int*   batch  = (const int*)  d_in[3];
    const float* nn1_w1 = (const float*)d_in[4];
    const float* nn1_b1 = (const float*)d_in[5];
    const float* nn1_w2 = (const float*)d_in[6];
    const float* nn1_b2 = (const float*)d_in[7];
    const float* root1  = (const float*)d_in[8];
    const float* bias1  = (const float*)d_in[9];
    const float* nn2_w1 = (const float*)d_in[10];
    const float* nn2_b1 = (const float*)d_in[11];
    const float* nn2_w2 = (const float*)d_in[12];
    const float* nn2_b2 = (const float*)d_in[13];
    const float* root2  = (const float*)d_in[14];
    const float* bias2  = (const float*)d_in[15];
    const float* lin1_w = (const float*)d_in[16];
    const float* lin1_b = (const float*)d_in[17];
    const float* lin2_w = (const float*)d_in[18];
    const float* lin2_b = (const float*)d_in[19];
    float* out = (float*)d_out;

    zero_all_kernel<<<(N_NODES * 8 + 255) / 256, 256>>>();
    prep_tabs_kernel<<<(B1TAB_N + 255) / 256, 256>>>(nn1_w2, nn1_b2, nn2_w2, nn2_b2);
    prep_xh2_kernel<<<(N_NODES * 8 + 255) / 256, 256>>>(x);

    const int egrid = (WTILES1 + 7) / 8;   // 1563 blocks of 8 warp-tiles

    // layer 1
    edge1_z_kernel<<<egrid, 256>>>(ea, ei, nn1_w1, nn1_b1);

    // node update 1 -> fp16 h1
    node1_kernel<<<N_NODES / 16, 256>>>(x, root1, bias1);

    // layer 2
    edge2_z_kernel<<<egrid, 256>>>(ea, ei, nn2_w1, nn2_b1);

    // node update 2 + pooling
    node2_pool_kernel<<<(N_NODES / 2 * 32 + 255) / 256, 256>>>(batch, root2, bias2);

    // readout
    readout_kernel<<<(N_GRAPHS + 255) / 256, 256>>>(lin1_w, lin1_b, lin2_w, lin2_b, out);
}